// round 8
// baseline (speedup 1.0000x reference)
#include <cuda_runtime.h>
#include <cuda_bf16.h>
#include <cstdint>

#define B_ 4
#define S_ 4096
#define D_ 512
#define M1 (B_*S_)   // 16384

// ---------------- scratch (device globals: the sanctioned no-alloc path) ----
__device__ float         g_X   [M1*D_];              // tf32-rounded xs
__device__ float         g_Wk2 [D_*D_];              // tf32-rounded Wk
__device__ float         g_Wq2 [D_*D_];              // tf32-rounded Wq
__device__ float         g_K   [B_*S_*D_];
__device__ float         g_Q   [B_*S_*D_];
__device__ float         g_VL  [B_*S_*D_];
__device__ __nv_bfloat16 g_E   [(size_t)B_*S_*S_];   // exp(qk/512), bf16
__device__ float         g_part[B_*8*S_];            // partial column sums
__device__ float         g_Linv[B_*S_];
__device__ float         g_r   [B_*S_];
__device__ float         g_Wc  [D_*D_];
__device__ float         g_bc  [D_];

// ---------------- helpers ---------------------------------------------------
__device__ __forceinline__ uint32_t f2tf(float x){
    uint32_t r; asm("cvt.rna.tf32.f32 %0, %1;" : "=r"(r) : "f"(x)); return r;
}
__device__ __forceinline__ float rnd_tf32(float x){
    return __uint_as_float(f2tf(x));
}
__device__ __forceinline__ void mma8(float c[4], const uint32_t a[4], const uint32_t b[2]){
    asm volatile(
        "mma.sync.aligned.m16n8k8.row.col.f32.tf32.tf32.f32 "
        "{%0,%1,%2,%3}, {%4,%5,%6,%7}, {%8,%9}, {%0,%1,%2,%3};"
        : "+f"(c[0]), "+f"(c[1]), "+f"(c[2]), "+f"(c[3])
        : "r"(a[0]), "r"(a[1]), "r"(a[2]), "r"(a[3]), "r"(b[0]), "r"(b[1]));
}
__device__ __forceinline__ void cp16(uint32_t dst, const void* src){
    asm volatile("cp.async.cg.shared.global [%0], [%1], 16;" :: "r"(dst), "l"(src) : "memory");
}
__device__ __forceinline__ void cp_commit(){
    asm volatile("cp.async.commit_group;" ::: "memory");
}
__device__ __forceinline__ void cp_wait0(){
    asm volatile("cp.async.wait_group 0;" ::: "memory");
}

// ---------------- prepass: round to tf32 (rna) -------------------------------
__global__ void round_tf32(const float4* __restrict__ src, float4* __restrict__ dst){
    int i = blockIdx.x*256 + threadIdx.x;
    float4 v = src[i];
    v.x = rnd_tf32(v.x); v.y = rnd_tf32(v.y);
    v.z = rnd_tf32(v.z); v.w = rnd_tf32(v.w);
    dst[i] = v;
}

// ---------------- Wc = Wl @ Wv (fp32, tiny; tf32-rounded at store) -----------
__global__ void wc_gemm(const float* __restrict__ Wl, const float* __restrict__ Wv,
                        float* __restrict__ Wc){
    __shared__ float sL[16][16];
    __shared__ float sV[16][17];
    int j = blockIdx.y*16 + threadIdx.y;
    int i = blockIdx.x*16 + threadIdx.x;
    float acc = 0.f;
    for (int k0 = 0; k0 < D_; k0 += 16){
        sL[threadIdx.y][threadIdx.x] = Wl[j*D_ + k0 + threadIdx.x];
        sV[threadIdx.y][threadIdx.x] = Wv[(k0 + threadIdx.y)*D_ + i];
        __syncthreads();
        #pragma unroll
        for (int k = 0; k < 16; k++) acc += sL[threadIdx.y][k]*sV[k][threadIdx.x];
        __syncthreads();
    }
    Wc[j*D_ + i] = rnd_tf32(acc);
}

// ---------------- bc = Wl @ bv ----------------------------------------------
__global__ void bc_kernel(const float* __restrict__ Wl, const float* __restrict__ bv,
                          float* __restrict__ bc){
    int j = blockIdx.x;
    __shared__ float red[128];
    float a = 0.f;
    for (int k = threadIdx.x; k < D_; k += 128) a += Wl[j*D_ + k]*bv[k];
    red[threadIdx.x] = a; __syncthreads();
    for (int s = 64; s > 0; s >>= 1){
        if (threadIdx.x < s) red[threadIdx.x] += red[threadIdx.x + s];
        __syncthreads();
    }
    if (threadIdx.x == 0) bc[j] = red[0];
}

// ---------------- cp.async double-buffered tf32 mainloop ---------------------
// Computes a 128x128 tile of A[128,512] @ B[128,512]^T with 8 warps (64x32 each).
// Inputs must already be tf32-rounded floats; copied raw via cp.async (lossless).
// K fixed at 512 (16 iters of BK=32). smem layout per stage: A 128x36 u32, B same.
#define LDT 36                       // (32+4): all fragment LDS conflict-free
#define STG_U32 (2*128*LDT)          // 9216 u32 per stage (A+B)
#define SMEM_BYTES (2*STG_U32*4)     // 73728 B, 2 stages

__device__ __forceinline__ void mainloop_512(const float* __restrict__ A,
                                             const float* __restrict__ B,
                                             float acc[4][4][4], uint32_t* sm)
{
    const int tid  = threadIdx.x;
    const int row  = tid >> 1;            // 0..127
    const int colf = (tid & 1) * 16;      // float column base (0 or 16)
    const float* gA = A + row*512 + colf;
    const float* gB = B + row*512 + colf;
    uint32_t sbase = (uint32_t)__cvta_generic_to_shared(sm);
    uint32_t dA = sbase + (uint32_t)(row*LDT + colf)*4u;
    uint32_t dB = dA + 128u*LDT*4u;

    // prologue: stage 0
    #pragma unroll
    for (int c = 0; c < 4; c++){
        cp16(dA + c*16, gA + c*4);
        cp16(dB + c*16, gB + c*4);
    }
    cp_commit();

    const int lane = tid & 31, warp = tid >> 5;
    const int wm = (warp & 1)*64, wn = (warp >> 1)*32;
    const int g = lane >> 2, t = lane & 3;

    for (int i = 0; i < 16; i++){
        cp_wait0();
        __syncthreads();
        if (i < 15){
            int st = (i + 1) & 1;
            const float* pA = gA + (i+1)*32;
            const float* pB = gB + (i+1)*32;
            uint32_t qA = dA + (uint32_t)st*STG_U32*4u;
            uint32_t qB = dB + (uint32_t)st*STG_U32*4u;
            #pragma unroll
            for (int c = 0; c < 4; c++){
                cp16(qA + c*16, pA + c*4);
                cp16(qB + c*16, pB + c*4);
            }
            cp_commit();
        }
        const uint32_t* sA = sm + (i & 1)*STG_U32;
        const uint32_t* sB = sA + 128*LDT;
        #pragma unroll
        for (int kk = 0; kk < 32; kk += 8){
            uint32_t af[4][4], bf[4][2];
            #pragma unroll
            for (int mi = 0; mi < 4; mi++){
                int r = wm + mi*16 + g;
                af[mi][0] = sA[ r    *LDT + kk + t    ];
                af[mi][1] = sA[(r+8) *LDT + kk + t    ];
                af[mi][2] = sA[ r    *LDT + kk + t + 4];
                af[mi][3] = sA[(r+8) *LDT + kk + t + 4];
            }
            #pragma unroll
            for (int ni = 0; ni < 4; ni++){
                int rn = wn + ni*8 + g;
                bf[ni][0] = sB[rn*LDT + kk + t    ];
                bf[ni][1] = sB[rn*LDT + kk + t + 4];
            }
            #pragma unroll
            for (int mi = 0; mi < 4; mi++)
                #pragma unroll
                for (int ni = 0; ni < 4; ni++)
                    mma8(acc[mi][ni], af[mi], bf[ni]);
        }
    }
}

// ---------------- fused QKV: z=0 -> K (rounded), z=1 -> Q (rounded), z=2 -> VL
__global__ void __launch_bounds__(256, 2)
gemm_qkv(const float* __restrict__ X,
         const float* __restrict__ W0, const float* __restrict__ W1,
         const float* __restrict__ W2,
         const float* __restrict__ c0, const float* __restrict__ c1,
         const float* __restrict__ c2,
         float* __restrict__ O0, float* __restrict__ O1, float* __restrict__ O2)
{
    extern __shared__ uint32_t sm[];
    const int z = blockIdx.z;
    const float* W    = (z == 0) ? W0 : (z == 1) ? W1 : W2;
    const float* bias = (z == 0) ? c0 : (z == 1) ? c1 : c2;
    float*       O    = (z == 0) ? O0 : (z == 1) ? O1 : O2;
    const int bm = blockIdx.y*128, bn = blockIdx.x*128;

    float acc[4][4][4];
    #pragma unroll
    for (int i = 0; i < 4; i++)
        #pragma unroll
        for (int j = 0; j < 4; j++)
            #pragma unroll
            for (int c = 0; c < 4; c++) acc[i][j][c] = 0.f;

    mainloop_512(X + (long long)bm*512, W + (long long)bn*512, acc, sm);

    const int lane = threadIdx.x & 31, warp = threadIdx.x >> 5;
    const int wm = (warp & 1)*64, wn = (warp >> 1)*32;
    const int g = lane >> 2, t = lane & 3;
    const bool rnd = (z < 2);

    #pragma unroll
    for (int mi = 0; mi < 4; mi++){
        int r0 = bm + wm + mi*16 + g;
        #pragma unroll
        for (int ni = 0; ni < 4; ni++){
            int c = bn + wn + ni*8 + 2*t;
            float b0 = bias[c], b1 = bias[c+1];
            float v0 = acc[mi][ni][0] + b0, v1 = acc[mi][ni][1] + b1;
            float v2 = acc[mi][ni][2] + b0, v3 = acc[mi][ni][3] + b1;
            if (rnd){
                v0 = rnd_tf32(v0); v1 = rnd_tf32(v1);
                v2 = rnd_tf32(v2); v3 = rnd_tf32(v3);
            }
            *(float2*)(O + (long long)r0*D_ + c)     = make_float2(v0, v1);
            *(float2*)(O + (long long)(r0+8)*D_ + c) = make_float2(v2, v3);
        }
    }
}

// ---------------- E[b] = bf16(exp((K[b] @ Q[b]^T)/512)) ----------------------
__global__ void __launch_bounds__(256, 2)
gemm_exp(const float* __restrict__ Kp, const float* __restrict__ Qp,
         __nv_bfloat16* __restrict__ E)
{
    extern __shared__ uint32_t sm[];
    const long long bz = blockIdx.z;
    const float* A = Kp + bz*(long long)S_*D_;
    const float* B = Qp + bz*(long long)S_*D_;
    __nv_bfloat16* Eo = E + bz*(long long)S_*S_;
    const int bm = blockIdx.y*128, bn = blockIdx.x*128;

    float acc[4][4][4];
    #pragma unroll
    for (int i = 0; i < 4; i++)
        #pragma unroll
        for (int j = 0; j < 4; j++)
            #pragma unroll
            for (int c = 0; c < 4; c++) acc[i][j][c] = 0.f;

    mainloop_512(A + (long long)bm*512, B + (long long)bn*512, acc, sm);

    const int lane = threadIdx.x & 31, warp = threadIdx.x >> 5;
    const int wm = (warp & 1)*64, wn = (warp >> 1)*32;
    const int g = lane >> 2, t = lane & 3;
    const float inv = 1.0f/512.0f;

    #pragma unroll
    for (int mi = 0; mi < 4; mi++){
        int r0 = bm + wm + mi*16 + g;
        #pragma unroll
        for (int ni = 0; ni < 4; ni++){
            int c = bn + wn + ni*8 + 2*t;
            float* ac = acc[mi][ni];
            *(__nv_bfloat162*)(Eo + (long long)r0*S_ + c) =
                __floats2bfloat162_rn(__expf(ac[0]*inv), __expf(ac[1]*inv));
            *(__nv_bfloat162*)(Eo + (long long)(r0+8)*S_ + c) =
                __floats2bfloat162_rn(__expf(ac[2]*inv), __expf(ac[3]*inv));
        }
    }
}

// ---------------- column-sum partials (deterministic, no atomics) -----------
__global__ void colsum_part(const __nv_bfloat16* __restrict__ E, float* __restrict__ part){
    int e = blockIdx.x*256 + threadIdx.x;
    int chunk = blockIdx.y, b = blockIdx.z;
    const __nv_bfloat16* p = E + (long long)b*S_*S_ + (long long)chunk*512*S_ + e;
    float acc = 0.f;
    #pragma unroll 8
    for (int s = 0; s < 512; s++) acc += __bfloat162float(p[(long long)s*S_]);
    part[(b*8 + chunk)*S_ + e] = acc;
}

__global__ void linv_kernel(const float* __restrict__ part, float* __restrict__ Linv){
    int i = blockIdx.x*256 + threadIdx.x;          // b*S + e, 16384 total
    int b = i >> 12, e = i & (S_-1);
    float s = 0.f;
    #pragma unroll
    for (int c = 0; c < 8; c++) s += part[(b*8 + c)*S_ + e];
    Linv[i] = 1.0f / s;
}

// ---------------- row-sum of E * Linv ---------------------------------------
__global__ void rowsum_kernel(const __nv_bfloat16* __restrict__ E,
                              const float* __restrict__ Linv, float* __restrict__ r){
    int s = blockIdx.x, b = blockIdx.y, tid = threadIdx.x;
    const __nv_bfloat162* row2 = (const __nv_bfloat162*)(E + ((long long)b*S_ + s)*S_);
    const float2* li2 = (const float2*)(Linv + b*S_);
    float acc = 0.f;
    #pragma unroll 4
    for (int i = tid; i < S_/2; i += 256){
        float2 v = __bfloat1622float2(row2[i]);
        float2 l = li2[i];
        acc += v.x*l.x + v.y*l.y;
    }
    __shared__ float red[256];
    red[tid] = acc; __syncthreads();
    for (int st = 128; st > 0; st >>= 1){
        if (tid < st) red[tid] += red[tid + st];
        __syncthreads();
    }
    if (tid == 0) r[(long long)b*S_ + s] = red[0];
}

// ---------------- out = tanh(r * VL + bl) -----------------------------------
__global__ void out_kernel(const float* __restrict__ VL, const float* __restrict__ r,
                           const float* __restrict__ bl, float* __restrict__ out){
    long long i = (long long)blockIdx.x*256 + threadIdx.x;   // one float4 each
    float4 v = ((const float4*)VL)[i];
    float rv = r[i >> 7];
    float4 b4 = ((const float4*)bl)[(int)(i & 127)];
    float4 o;
    o.x = tanhf(rv*v.x + b4.x);
    o.y = tanhf(rv*v.y + b4.y);
    o.z = tanhf(rv*v.z + b4.z);
    o.w = tanhf(rv*v.w + b4.w);
    ((float4*)out)[i] = o;
}

// ---------------- launcher --------------------------------------------------
extern "C" void kernel_launch(void* const* d_in, const int* in_sizes, int n_in,
                              void* d_out, int out_size){
    const float* xs = (const float*)d_in[0];
    const float* Wk = (const float*)d_in[1];
    const float* bk = (const float*)d_in[2];
    const float* Wq = (const float*)d_in[3];
    const float* bq = (const float*)d_in[4];
    const float* Wv = (const float*)d_in[5];
    const float* bv = (const float*)d_in[6];
    const float* Wl = (const float*)d_in[7];
    const float* bl = (const float*)d_in[8];
    float* out = (float*)d_out;
    (void)in_sizes; (void)n_in; (void)out_size;

    float *pX, *pWk2, *pWq2, *pK, *pQ, *pVL, *pPart, *pLinv, *pR, *pWc, *pBc;
    __nv_bfloat16* pE;
    cudaGetSymbolAddress((void**)&pX,    g_X);
    cudaGetSymbolAddress((void**)&pWk2,  g_Wk2);
    cudaGetSymbolAddress((void**)&pWq2,  g_Wq2);
    cudaGetSymbolAddress((void**)&pK,    g_K);
    cudaGetSymbolAddress((void**)&pQ,    g_Q);
    cudaGetSymbolAddress((void**)&pVL,   g_VL);
    cudaGetSymbolAddress((void**)&pE,    g_E);
    cudaGetSymbolAddress((void**)&pPart, g_part);
    cudaGetSymbolAddress((void**)&pLinv, g_Linv);
    cudaGetSymbolAddress((void**)&pR,    g_r);
    cudaGetSymbolAddress((void**)&pWc,   g_Wc);
    cudaGetSymbolAddress((void**)&pBc,   g_bc);

    static bool attr_done = false;
    if (!attr_done){
        cudaFuncSetAttribute(gemm_qkv, cudaFuncAttributeMaxDynamicSharedMemorySize, SMEM_BYTES);
        cudaFuncSetAttribute(gemm_exp, cudaFuncAttributeMaxDynamicSharedMemorySize, SMEM_BYTES);
        attr_done = true;
    }

    // 0) tf32-round inputs once (so GEMM mainloops copy raw, losslessly)
    round_tf32<<<(M1*D_/4)/256, 256>>>((const float4*)xs, (float4*)pX);
    round_tf32<<<(D_*D_/4)/256, 256>>>((const float4*)Wk, (float4*)pWk2);
    round_tf32<<<(D_*D_/4)/256, 256>>>((const float4*)Wq, (float4*)pWq2);

    // 1) combined last-layer weights: Wc = round(Wl@Wv), bc = Wl@bv
    wc_gemm<<<dim3(D_/16, D_/16), dim3(16,16)>>>(Wl, Wv, pWc);
    bc_kernel<<<D_, 128>>>(Wl, bv, pBc);

    // 2) fused K/Q/VL = X @ {Wk,Wq,Wc}^T + {bk,bq,bc}  (K,Q rounded to tf32)
    gemm_qkv<<<dim3(D_/128, M1/128, 3), 256, SMEM_BYTES>>>(
        pX, pWk2, pWq2, pWc, bk, bq, pBc, pK, pQ, pVL);

    // 3) E[b] = exp((K[b] @ Q[b]^T)/512), bf16   (batched over grid.z)
    gemm_exp<<<dim3(S_/128, S_/128, B_), 256, SMEM_BYTES>>>(pK, pQ, pE);

    // 4) Linv[b,e] = 1 / sum_s E ;  r[b,s] = sum_e E * Linv
    colsum_part<<<dim3(S_/256, 8, B_), 256>>>(pE, pPart);
    linv_kernel<<<(B_*S_)/256, 256>>>(pPart, pLinv);
    rowsum_kernel<<<dim3(S_, B_), 256>>>(pE, pLinv, pR);

    // 5) out = tanh(r * VL + bl)
    out_kernel<<<(B_*S_*D_/4)/256, 256>>>(pVL, pR, bl, out);
}

// round 9
// speedup vs baseline: 1.1621x; 1.1621x over previous
#include <cuda_runtime.h>
#include <cuda_bf16.h>
#include <cstdint>

#define B_ 4
#define S_ 4096
#define D_ 512
#define M1 (B_*S_)   // 16384

// ---------------- scratch (device globals: the sanctioned no-alloc path) ----
__device__ float         g_K   [B_*S_*D_];
__device__ float         g_Q   [B_*S_*D_];
__device__ float         g_VL  [B_*S_*D_];
__device__ __nv_bfloat16 g_E   [(size_t)B_*S_*S_];   // exp(qk/512), bf16
__device__ float         g_part[B_*8*S_];            // partial column sums
__device__ float         g_Linv[B_*S_];
__device__ float         g_r   [B_*S_];
__device__ float         g_Wc  [D_*D_];
__device__ float         g_bc  [D_];

// ---------------- helpers ---------------------------------------------------
__device__ __forceinline__ uint32_t f2tf(float x){
    uint32_t r; asm("cvt.rna.tf32.f32 %0, %1;" : "=r"(r) : "f"(x)); return r;
}
__device__ __forceinline__ void mma8(float c[4], const uint32_t a[4], const uint32_t b[2]){
    asm volatile(
        "mma.sync.aligned.m16n8k8.row.col.f32.tf32.tf32.f32 "
        "{%0,%1,%2,%3}, {%4,%5,%6,%7}, {%8,%9}, {%0,%1,%2,%3};"
        : "+f"(c[0]), "+f"(c[1]), "+f"(c[2]), "+f"(c[3])
        : "r"(a[0]), "r"(a[1]), "r"(a[2]), "r"(a[3]), "r"(b[0]), "r"(b[1]));
}

// ---------------- Wc = Wl @ Wv (fp32, register-blocked 64x64 tiles) ----------
__global__ void __launch_bounds__(256)
wc_gemm(const float* __restrict__ Wl, const float* __restrict__ Wv,
        float* __restrict__ Wc){
    __shared__ float sL[16][65];   // sL[k][j]  (j = output row within tile)
    __shared__ float sV[16][65];   // sV[k][i]  (i = output col within tile)
    const int bj = blockIdx.y*64, bi = blockIdx.x*64;
    const int tx = threadIdx.x & 15, ty = threadIdx.x >> 4;

    float acc[4][4];
    #pragma unroll
    for (int m = 0; m < 4; m++)
        #pragma unroll
        for (int n = 0; n < 4; n++) acc[m][n] = 0.f;

    for (int k0 = 0; k0 < D_; k0 += 16){
        #pragma unroll
        for (int p = 0; p < 4; p++){
            int idx = threadIdx.x + p*256;          // 0..1023
            int r  = idx >> 4, c  = idx & 15;       // Wl tile: 64 rows x 16 k
            sL[c][r] = Wl[(bj + r)*D_ + k0 + c];
            int r2 = idx >> 6, c2 = idx & 63;       // Wv tile: 16 k x 64 cols
            sV[r2][c2] = Wv[(k0 + r2)*D_ + bi + c2];
        }
        __syncthreads();
        #pragma unroll
        for (int k = 0; k < 16; k++){
            float a[4], b[4];
            #pragma unroll
            for (int m = 0; m < 4; m++) a[m] = sL[k][ty*4 + m];
            #pragma unroll
            for (int n = 0; n < 4; n++) b[n] = sV[k][tx*4 + n];
            #pragma unroll
            for (int m = 0; m < 4; m++)
                #pragma unroll
                for (int n = 0; n < 4; n++) acc[m][n] += a[m]*b[n];
        }
        __syncthreads();
    }
    #pragma unroll
    for (int m = 0; m < 4; m++)
        #pragma unroll
        for (int n = 0; n < 4; n++)
            Wc[(bj + ty*4 + m)*D_ + bi + tx*4 + n] = acc[m][n];
}

// ---------------- bc = Wl @ bv ----------------------------------------------
__global__ void bc_kernel(const float* __restrict__ Wl, const float* __restrict__ bv,
                          float* __restrict__ bc){
    int j = blockIdx.x;
    __shared__ float red[128];
    float a = 0.f;
    for (int k = threadIdx.x; k < D_; k += 128) a += Wl[j*D_ + k]*bv[k];
    red[threadIdx.x] = a; __syncthreads();
    for (int s = 64; s > 0; s >>= 1){
        if (threadIdx.x < s) red[threadIdx.x] += red[threadIdx.x + s];
        __syncthreads();
    }
    if (threadIdx.x == 0) bc[j] = red[0];
}

// ---------------- generic tf32 mma GEMM: C = A @ B^T (+epilogue) ------------
// A: [M,K] rm, B: [N,K] rm. All of M,N divisible by 128, K by 32 (true here).
// EPI 0: Cf[m,n] = acc + bias[n]            (fp32 out, ldc = N)
// EPI 1: Cb[m,n] = bf16(exp(acc/512))       (bf16 out, ldc = N)
#define BMT 128
#define BNT 128
#define BKT 32
#define LDT 36   // (BKT+4): fragment LDS conflict-free; STS done as 128-bit

template<int EPI>
__global__ void __launch_bounds__(256, 2)
gemm_tf32(const float* __restrict__ Ag, const float* __restrict__ Bg,
          const float* __restrict__ bias,
          float* __restrict__ Cf, __nv_bfloat16* __restrict__ Cb,
          int M, int N, int K,
          long long strA, long long strB, long long strC)
{
    __shared__ __align__(16) uint32_t sA[BMT*LDT];
    __shared__ __align__(16) uint32_t sB[BNT*LDT];

    const int tid  = threadIdx.x;
    const long long bz = blockIdx.z;
    const float* A  = Ag + bz*strA;
    const float* Bm = Bg + bz*strB;
    const int bm = blockIdx.y*BMT, bn = blockIdx.x*BNT;
    const int lane = tid & 31, warp = tid >> 5;
    const int wm = (warp & 1)*64, wn = (warp >> 1)*32;  // 2x4 warp grid, 64x32 tiles
    const int g = lane >> 2, t = lane & 3;
    const int lrow = tid >> 3, lcol = (tid & 7)*4;

    float acc[4][4][4];
    #pragma unroll
    for (int i = 0; i < 4; i++)
        #pragma unroll
        for (int j = 0; j < 4; j++)
            #pragma unroll
            for (int c = 0; c < 4; c++) acc[i][j][c] = 0.f;

    for (int k0 = 0; k0 < K; k0 += BKT){
        #pragma unroll
        for (int p = 0; p < 4; p++){
            int r = lrow + p*32;
            float4 va = *(const float4*)(A  + (long long)(bm + r)*K + k0 + lcol);
            uint4 ua = make_uint4(f2tf(va.x), f2tf(va.y), f2tf(va.z), f2tf(va.w));
            *(uint4*)&sA[r*LDT + lcol] = ua;             // STS.128, conflict-free
            float4 vb = *(const float4*)(Bm + (long long)(bn + r)*K + k0 + lcol);
            uint4 ub = make_uint4(f2tf(vb.x), f2tf(vb.y), f2tf(vb.z), f2tf(vb.w));
            *(uint4*)&sB[r*LDT + lcol] = ub;             // STS.128, conflict-free
        }
        __syncthreads();
        #pragma unroll
        for (int kk = 0; kk < BKT; kk += 8){
            uint32_t af[4][4], bf[4][2];
            #pragma unroll
            for (int mi = 0; mi < 4; mi++){
                int r = wm + mi*16 + g;
                af[mi][0] = sA[ r    *LDT + kk + t    ];
                af[mi][1] = sA[(r+8) *LDT + kk + t    ];
                af[mi][2] = sA[ r    *LDT + kk + t + 4];
                af[mi][3] = sA[(r+8) *LDT + kk + t + 4];
            }
            #pragma unroll
            for (int ni = 0; ni < 4; ni++){
                int rn = wn + ni*8 + g;
                bf[ni][0] = sB[rn*LDT + kk + t    ];
                bf[ni][1] = sB[rn*LDT + kk + t + 4];
            }
            #pragma unroll
            for (int mi = 0; mi < 4; mi++)
                #pragma unroll
                for (int ni = 0; ni < 4; ni++)
                    mma8(acc[mi][ni], af[mi], bf[ni]);
        }
        __syncthreads();
    }

    // epilogue
    #pragma unroll
    for (int mi = 0; mi < 4; mi++){
        int r0 = bm + wm + mi*16 + g;
        #pragma unroll
        for (int ni = 0; ni < 4; ni++){
            int c = bn + wn + ni*8 + 2*t;
            float* ac = acc[mi][ni];
            if (EPI == 0){
                float b0 = bias[c], b1 = bias[c+1];
                *(float2*)(Cf + (long long)r0*N + c)     = make_float2(ac[0]+b0, ac[1]+b1);
                *(float2*)(Cf + (long long)(r0+8)*N + c) = make_float2(ac[2]+b0, ac[3]+b1);
            } else {
                __nv_bfloat16* Co = Cb + bz*strC;
                const float inv = 1.0f/512.0f;
                *(__nv_bfloat162*)(Co + (long long)r0*N + c) =
                    __floats2bfloat162_rn(__expf(ac[0]*inv), __expf(ac[1]*inv));
                *(__nv_bfloat162*)(Co + (long long)(r0+8)*N + c) =
                    __floats2bfloat162_rn(__expf(ac[2]*inv), __expf(ac[3]*inv));
            }
        }
    }
}

// ---------------- column-sum partials (deterministic, no atomics) -----------
__global__ void colsum_part(const __nv_bfloat16* __restrict__ E, float* __restrict__ part){
    int e = blockIdx.x*256 + threadIdx.x;
    int chunk = blockIdx.y, b = blockIdx.z;
    const __nv_bfloat16* p = E + (long long)b*S_*S_ + (long long)chunk*512*S_ + e;
    float acc = 0.f;
    #pragma unroll 8
    for (int s = 0; s < 512; s++) acc += __bfloat162float(p[(long long)s*S_]);
    part[(b*8 + chunk)*S_ + e] = acc;
}

__global__ void linv_kernel(const float* __restrict__ part, float* __restrict__ Linv){
    int i = blockIdx.x*256 + threadIdx.x;          // b*S + e, 16384 total
    int b = i >> 12, e = i & (S_-1);
    float s = 0.f;
    #pragma unroll
    for (int c = 0; c < 8; c++) s += part[(b*8 + c)*S_ + e];
    Linv[i] = 1.0f / s;
}

// ---------------- row-sum of E * Linv ---------------------------------------
__global__ void rowsum_kernel(const __nv_bfloat16* __restrict__ E,
                              const float* __restrict__ Linv, float* __restrict__ r){
    int s = blockIdx.x, b = blockIdx.y, tid = threadIdx.x;
    const __nv_bfloat162* row2 = (const __nv_bfloat162*)(E + ((long long)b*S_ + s)*S_);
    const float2* li2 = (const float2*)(Linv + b*S_);
    float acc = 0.f;
    #pragma unroll 4
    for (int i = tid; i < S_/2; i += 256){
        float2 v = __bfloat1622float2(row2[i]);
        float2 l = li2[i];
        acc += v.x*l.x + v.y*l.y;
    }
    __shared__ float red[256];
    red[tid] = acc; __syncthreads();
    for (int st = 128; st > 0; st >>= 1){
        if (tid < st) red[tid] += red[tid + st];
        __syncthreads();
    }
    if (tid == 0) r[(long long)b*S_ + s] = red[0];
}

// ---------------- out = tanh(r * VL + bl) -----------------------------------
__global__ void out_kernel(const float* __restrict__ VL, const float* __restrict__ r,
                           const float* __restrict__ bl, float* __restrict__ out){
    long long i = (long long)blockIdx.x*256 + threadIdx.x;   // one float4 each
    float4 v = ((const float4*)VL)[i];
    float rv = r[i >> 7];                                    // (4i)/512
    float4 b4 = ((const float4*)bl)[(int)(i & 127)];         // (4i mod 512)/4
    float4 o;
    o.x = tanhf(rv*v.x + b4.x);
    o.y = tanhf(rv*v.y + b4.y);
    o.z = tanhf(rv*v.z + b4.z);
    o.w = tanhf(rv*v.w + b4.w);
    ((float4*)out)[i] = o;
}

// ---------------- launcher --------------------------------------------------
extern "C" void kernel_launch(void* const* d_in, const int* in_sizes, int n_in,
                              void* d_out, int out_size){
    const float* xs = (const float*)d_in[0];
    const float* Wk = (const float*)d_in[1];
    const float* bk = (const float*)d_in[2];
    const float* Wq = (const float*)d_in[3];
    const float* bq = (const float*)d_in[4];
    const float* Wv = (const float*)d_in[5];
    const float* bv = (const float*)d_in[6];
    const float* Wl = (const float*)d_in[7];
    const float* bl = (const float*)d_in[8];
    float* out = (float*)d_out;
    (void)in_sizes; (void)n_in; (void)out_size;

    float *pK, *pQ, *pVL, *pPart, *pLinv, *pR, *pWc, *pBc;
    __nv_bfloat16* pE;
    cudaGetSymbolAddress((void**)&pK,    g_K);
    cudaGetSymbolAddress((void**)&pQ,    g_Q);
    cudaGetSymbolAddress((void**)&pVL,   g_VL);
    cudaGetSymbolAddress((void**)&pE,    g_E);
    cudaGetSymbolAddress((void**)&pPart, g_part);
    cudaGetSymbolAddress((void**)&pLinv, g_Linv);
    cudaGetSymbolAddress((void**)&pR,    g_r);
    cudaGetSymbolAddress((void**)&pWc,   g_Wc);
    cudaGetSymbolAddress((void**)&pBc,   g_bc);

    // 1) combined last-layer weights: Wc = Wl@Wv, bc = Wl@bv      (launch 0,1)
    wc_gemm<<<dim3(D_/64, D_/64), 256>>>(Wl, Wv, pWc);
    bc_kernel<<<D_, 128>>>(Wl, bv, pBc);

    // 2) K, Q, VL = xs @ {Wk,Wq,Wc}^T + {bk,bq,bc}                (launch 2,3,4)
    gemm_tf32<0><<<dim3(D_/BNT, M1/BMT, 1), 256>>>(xs, Wk,  bk,  pK,  nullptr,
                                                   M1, D_, D_, 0, 0, 0);
    gemm_tf32<0><<<dim3(D_/BNT, M1/BMT, 1), 256>>>(xs, Wq,  bq,  pQ,  nullptr,
                                                   M1, D_, D_, 0, 0, 0);
    gemm_tf32<0><<<dim3(D_/BNT, M1/BMT, 1), 256>>>(xs, pWc, pBc, pVL, nullptr,
                                                   M1, D_, D_, 0, 0, 0);

    // 3) E[b] = exp((K[b] @ Q[b]^T)/512), bf16                    (launch 5 -> ncu)
    gemm_tf32<1><<<dim3(S_/BNT, S_/BMT, B_), 256>>>(pK, pQ, nullptr, nullptr, pE,
                                                    S_, S_, D_,
                                                    (long long)S_*D_, (long long)S_*D_,
                                                    (long long)S_*S_);

    // 4) Linv[b,e] = 1 / sum_s E ;  r[b,s] = sum_e E * Linv
    colsum_part<<<dim3(S_/256, 8, B_), 256>>>(pE, pPart);
    linv_kernel<<<(B_*S_)/256, 256>>>(pPart, pLinv);
    rowsum_kernel<<<dim3(S_, B_), 256>>>(pE, pLinv, pR);

    // 5) out = tanh(r * VL + bl)
    out_kernel<<<(B_*S_*D_/4)/256, 256>>>(pVL, pR, bl, out);
}

// round 12
// speedup vs baseline: 1.4915x; 1.2834x over previous
#include <cuda_runtime.h>
#include <cuda_bf16.h>
#include <cstdint>

#define B_ 4
#define S_ 4096
#define D_ 512
#define M1 (B_*S_)   // 16384

// ---------------- scratch (device globals: the sanctioned no-alloc path) ----
__device__ __nv_bfloat16 g_Xh [M1*D_];               // bf16 xs
__device__ __nv_bfloat16 g_Wkh[D_*D_];               // bf16 Wk
__device__ __nv_bfloat16 g_Wqh[D_*D_];               // bf16 Wq
__device__ __nv_bfloat16 g_Kh [B_*S_*D_];            // bf16 K
__device__ __nv_bfloat16 g_Qh [B_*S_*D_];            // bf16 Q
__device__ float         g_VL [B_*S_*D_];
__device__ __nv_bfloat16 g_E  [(size_t)B_*S_*S_];    // E[b][s][e] = exp(qk/512)
__device__ float         g_part[B_*8*S_];
__device__ float         g_Linv[B_*S_];
__device__ float         g_r  [B_*S_];
__device__ float         g_Wc [D_*D_];
__device__ float         g_bc [D_];

// ---------------- helpers ---------------------------------------------------
__device__ __forceinline__ uint32_t f2tf(float x){
    uint32_t r; asm("cvt.rna.tf32.f32 %0, %1;" : "=r"(r) : "f"(x)); return r;
}
__device__ __forceinline__ void mma_tf(float c[4], const uint32_t a[4], const uint32_t b[2]){
    asm volatile(
        "mma.sync.aligned.m16n8k8.row.col.f32.tf32.tf32.f32 "
        "{%0,%1,%2,%3}, {%4,%5,%6,%7}, {%8,%9}, {%0,%1,%2,%3};"
        : "+f"(c[0]), "+f"(c[1]), "+f"(c[2]), "+f"(c[3])
        : "r"(a[0]), "r"(a[1]), "r"(a[2]), "r"(a[3]), "r"(b[0]), "r"(b[1]));
}
__device__ __forceinline__ void mma_bf(float c[4], const uint32_t a[4], const uint32_t b[2]){
    asm volatile(
        "mma.sync.aligned.m16n8k16.row.col.f32.bf16.bf16.f32 "
        "{%0,%1,%2,%3}, {%4,%5,%6,%7}, {%8,%9}, {%0,%1,%2,%3};"
        : "+f"(c[0]), "+f"(c[1]), "+f"(c[2]), "+f"(c[3])
        : "r"(a[0]), "r"(a[1]), "r"(a[2]), "r"(a[3]), "r"(b[0]), "r"(b[1]));
}

// ---------------- float -> bf16 cast (8 elems/thread) ------------------------
__global__ void cvt_bf16(const float4* __restrict__ src, uint4* __restrict__ dst){
    int i = blockIdx.x*256 + threadIdx.x;
    float4 a = src[2*i], b = src[2*i+1];
    __nv_bfloat162 p0 = __floats2bfloat162_rn(a.x, a.y);
    __nv_bfloat162 p1 = __floats2bfloat162_rn(a.z, a.w);
    __nv_bfloat162 p2 = __floats2bfloat162_rn(b.x, b.y);
    __nv_bfloat162 p3 = __floats2bfloat162_rn(b.z, b.w);
    uint4 q;
    q.x = *(uint32_t*)&p0; q.y = *(uint32_t*)&p1;
    q.z = *(uint32_t*)&p2; q.w = *(uint32_t*)&p3;
    dst[i] = q;
}

// ---------------- Wc = Wl @ Wv (fp32, register-blocked 64x64 tiles) ----------
__global__ void __launch_bounds__(256)
wc_gemm(const float* __restrict__ Wl, const float* __restrict__ Wv,
        float* __restrict__ Wc){
    __shared__ float sL[16][65];
    __shared__ float sV[16][65];
    const int bj = blockIdx.y*64, bi = blockIdx.x*64;
    const int tx = threadIdx.x & 15, ty = threadIdx.x >> 4;

    float acc[4][4];
    #pragma unroll
    for (int m = 0; m < 4; m++)
        #pragma unroll
        for (int n = 0; n < 4; n++) acc[m][n] = 0.f;

    for (int k0 = 0; k0 < D_; k0 += 16){
        #pragma unroll
        for (int p = 0; p < 4; p++){
            int idx = threadIdx.x + p*256;
            int r  = idx >> 4, c  = idx & 15;
            sL[c][r] = Wl[(bj + r)*D_ + k0 + c];
            int r2 = idx >> 6, c2 = idx & 63;
            sV[r2][c2] = Wv[(k0 + r2)*D_ + bi + c2];
        }
        __syncthreads();
        #pragma unroll
        for (int k = 0; k < 16; k++){
            float a[4], b[4];
            #pragma unroll
            for (int m = 0; m < 4; m++) a[m] = sL[k][ty*4 + m];
            #pragma unroll
            for (int n = 0; n < 4; n++) b[n] = sV[k][tx*4 + n];
            #pragma unroll
            for (int m = 0; m < 4; m++)
                #pragma unroll
                for (int n = 0; n < 4; n++) acc[m][n] += a[m]*b[n];
        }
        __syncthreads();
    }
    #pragma unroll
    for (int m = 0; m < 4; m++)
        #pragma unroll
        for (int n = 0; n < 4; n++)
            Wc[(bj + ty*4 + m)*D_ + bi + tx*4 + n] = acc[m][n];
}

// ---------------- bc = Wl @ bv ----------------------------------------------
__global__ void bc_kernel(const float* __restrict__ Wl, const float* __restrict__ bv,
                          float* __restrict__ bc){
    int j = blockIdx.x;
    __shared__ float red[128];
    float a = 0.f;
    for (int k = threadIdx.x; k < D_; k += 128) a += Wl[j*D_ + k]*bv[k];
    red[threadIdx.x] = a; __syncthreads();
    for (int s = 64; s > 0; s >>= 1){
        if (threadIdx.x < s) red[threadIdx.x] += red[threadIdx.x + s];
        __syncthreads();
    }
    if (threadIdx.x == 0) bc[j] = red[0];
}

// ---------------- tf32 mma GEMM (VL path only): Cf = A @ B^T + bias ---------
#define BMT 128
#define BNT 128
#define LDT 36   // u32 row pitch with +4 pad: conflict-free LDS/STS

__global__ void __launch_bounds__(256, 2)
gemm_tf32(const float* __restrict__ Ag, const float* __restrict__ Bg,
          const float* __restrict__ bias, float* __restrict__ Cf,
          int M, int N, int K)
{
    __shared__ __align__(16) uint32_t sA[BMT*LDT];
    __shared__ __align__(16) uint32_t sB[BNT*LDT];

    const int tid  = threadIdx.x;
    const int bm = blockIdx.y*BMT, bn = blockIdx.x*BNT;
    const int lane = tid & 31, warp = tid >> 5;
    const int wm = (warp & 1)*64, wn = (warp >> 1)*32;
    const int g = lane >> 2, t = lane & 3;
    const int lrow = tid >> 3, lcol = (tid & 7)*4;

    float acc[4][4][4];
    #pragma unroll
    for (int i = 0; i < 4; i++)
        #pragma unroll
        for (int j = 0; j < 4; j++)
            #pragma unroll
            for (int c = 0; c < 4; c++) acc[i][j][c] = 0.f;

    for (int k0 = 0; k0 < K; k0 += 32){
        #pragma unroll
        for (int p = 0; p < 4; p++){
            int r = lrow + p*32;
            float4 va = *(const float4*)(Ag + (long long)(bm + r)*K + k0 + lcol);
            *(uint4*)&sA[r*LDT + lcol] = make_uint4(f2tf(va.x), f2tf(va.y), f2tf(va.z), f2tf(va.w));
            float4 vb = *(const float4*)(Bg + (long long)(bn + r)*K + k0 + lcol);
            *(uint4*)&sB[r*LDT + lcol] = make_uint4(f2tf(vb.x), f2tf(vb.y), f2tf(vb.z), f2tf(vb.w));
        }
        __syncthreads();
        #pragma unroll
        for (int kk = 0; kk < 32; kk += 8){
            uint32_t af[4][4], bf[4][2];
            #pragma unroll
            for (int mi = 0; mi < 4; mi++){
                int r = wm + mi*16 + g;
                af[mi][0] = sA[ r    *LDT + kk + t    ];
                af[mi][1] = sA[(r+8) *LDT + kk + t    ];
                af[mi][2] = sA[ r    *LDT + kk + t + 4];
                af[mi][3] = sA[(r+8) *LDT + kk + t + 4];
            }
            #pragma unroll
            for (int ni = 0; ni < 4; ni++){
                int rn = wn + ni*8 + g;
                bf[ni][0] = sB[rn*LDT + kk + t    ];
                bf[ni][1] = sB[rn*LDT + kk + t + 4];
            }
            #pragma unroll
            for (int mi = 0; mi < 4; mi++)
                #pragma unroll
                for (int ni = 0; ni < 4; ni++)
                    mma_tf(acc[mi][ni], af[mi], bf[ni]);
        }
        __syncthreads();
    }

    #pragma unroll
    for (int mi = 0; mi < 4; mi++){
        int r0 = bm + wm + mi*16 + g;
        #pragma unroll
        for (int ni = 0; ni < 4; ni++){
            int c = bn + wn + ni*8 + 2*t;
            float* ac = acc[mi][ni];
            float b0 = bias[c], b1 = bias[c+1];
            *(float2*)(Cf + (long long)r0*N + c)     = make_float2(ac[0]+b0, ac[1]+b1);
            *(float2*)(Cf + (long long)(r0+8)*N + c) = make_float2(ac[2]+b0, ac[3]+b1);
        }
    }
}

// ---------------- bf16 m16n8k16 GEMM: C = A @ B^T (+epilogue) ---------------
// A: [M,K] bf16 rm, B: [N,K] bf16 rm. BK=64 bf16 (= 32 u32 cols, LDT pitch 36).
// EPI 1: Cb = bf16(acc + bias)     (K, Q)
// EPI 2: Cb = bf16(exp(acc/512))   (E, batched via grid.z)
template<int EPI>
__global__ void __launch_bounds__(256, 2)
gemm_bf16(const __nv_bfloat16* __restrict__ Ag, const __nv_bfloat16* __restrict__ Bg,
          const float* __restrict__ bias, __nv_bfloat16* __restrict__ Cb,
          int M, int N, int K,
          long long strA, long long strB, long long strC)
{
    __shared__ __align__(16) uint32_t sA[BMT*LDT];
    __shared__ __align__(16) uint32_t sB[BNT*LDT];

    const int tid  = threadIdx.x;
    const long long bz = blockIdx.z;
    const __nv_bfloat16* A  = Ag + bz*strA;
    const __nv_bfloat16* Bm = Bg + bz*strB;
    const int bm = blockIdx.y*BMT, bn = blockIdx.x*BNT;
    const int lane = tid & 31, warp = tid >> 5;
    const int wm = (warp & 1)*64, wn = (warp >> 1)*32;
    const int g = lane >> 2, t = lane & 3;
    const int lrow = tid >> 1;                 // 0..127 (staging row)
    const int lch  = (tid & 1)*4;              // 2 threads/row, 4 16B-chunks each

    float acc[4][4][4];
    #pragma unroll
    for (int i = 0; i < 4; i++)
        #pragma unroll
        for (int j = 0; j < 4; j++)
            #pragma unroll
            for (int c = 0; c < 4; c++) acc[i][j][c] = 0.f;

    for (int k0 = 0; k0 < K; k0 += 64){        // 64 bf16 per tile
        #pragma unroll
        for (int c = 0; c < 4; c++){
            int ch = lch + c;                  // 16B chunk 0..7 within row
            *(uint4*)&sA[lrow*LDT + ch*4] =
                *(const uint4*)(A  + (long long)(bm + lrow)*K + k0 + ch*8);
            *(uint4*)&sB[lrow*LDT + ch*4] =
                *(const uint4*)(Bm + (long long)(bn + lrow)*K + k0 + ch*8);
        }
        __syncthreads();
        #pragma unroll
        for (int kk = 0; kk < 32; kk += 8){    // each kk = k16 step
            uint32_t af[4][4], bf[4][2];
            #pragma unroll
            for (int mi = 0; mi < 4; mi++){
                int r = wm + mi*16 + g;
                af[mi][0] = sA[ r    *LDT + kk + t    ];
                af[mi][1] = sA[(r+8) *LDT + kk + t    ];
                af[mi][2] = sA[ r    *LDT + kk + t + 4];
                af[mi][3] = sA[(r+8) *LDT + kk + t + 4];
            }
            #pragma unroll
            for (int ni = 0; ni < 4; ni++){
                int rn = wn + ni*8 + g;
                bf[ni][0] = sB[rn*LDT + kk + t    ];
                bf[ni][1] = sB[rn*LDT + kk + t + 4];
            }
            #pragma unroll
            for (int mi = 0; mi < 4; mi++)
                #pragma unroll
                for (int ni = 0; ni < 4; ni++)
                    mma_bf(acc[mi][ni], af[mi], bf[ni]);
        }
        __syncthreads();
    }

    __nv_bfloat16* Co = Cb + bz*strC;
    #pragma unroll
    for (int mi = 0; mi < 4; mi++){
        int r0 = bm + wm + mi*16 + g;
        #pragma unroll
        for (int ni = 0; ni < 4; ni++){
            int c = bn + wn + ni*8 + 2*t;
            float* ac = acc[mi][ni];
            if (EPI == 1){
                float b0 = bias[c], b1 = bias[c+1];
                *(__nv_bfloat162*)(Co + (long long)r0*N + c) =
                    __floats2bfloat162_rn(ac[0]+b0, ac[1]+b1);
                *(__nv_bfloat162*)(Co + (long long)(r0+8)*N + c) =
                    __floats2bfloat162_rn(ac[2]+b0, ac[3]+b1);
            } else {
                const float inv = 1.0f/512.0f;
                *(__nv_bfloat162*)(Co + (long long)r0*N + c) =
                    __floats2bfloat162_rn(__expf(ac[0]*inv), __expf(ac[1]*inv));
                *(__nv_bfloat162*)(Co + (long long)(r0+8)*N + c) =
                    __floats2bfloat162_rn(__expf(ac[2]*inv), __expf(ac[3]*inv));
            }
        }
    }
}

// ---------------- column-sum partials (deterministic, no atomics) -----------
__global__ void colsum_part(const __nv_bfloat16* __restrict__ E, float* __restrict__ part){
    int e = blockIdx.x*256 + threadIdx.x;
    int chunk = blockIdx.y, b = blockIdx.z;
    const __nv_bfloat16* p = E + (long long)b*S_*S_ + (long long)chunk*512*S_ + e;
    float acc = 0.f;
    #pragma unroll 8
    for (int s = 0; s < 512; s++) acc += __bfloat162float(p[(long long)s*S_]);
    part[(b*8 + chunk)*S_ + e] = acc;
}

__global__ void linv_kernel(const float* __restrict__ part, float* __restrict__ Linv){
    int i = blockIdx.x*256 + threadIdx.x;
    int b = i >> 12, e = i & (S_-1);
    float s = 0.f;
    #pragma unroll
    for (int c = 0; c < 8; c++) s += part[(b*8 + c)*S_ + e];
    Linv[i] = 1.0f / s;
}

// ---------------- row-sum of E * Linv ---------------------------------------
__global__ void rowsum_kernel(const __nv_bfloat16* __restrict__ E,
                              const float* __restrict__ Linv, float* __restrict__ r){
    int s = blockIdx.x, b = blockIdx.y, tid = threadIdx.x;
    const __nv_bfloat162* row2 = (const __nv_bfloat162*)(E + ((long long)b*S_ + s)*S_);
    const float2* li2 = (const float2*)(Linv + b*S_);
    float acc = 0.f;
    #pragma unroll 4
    for (int i = tid; i < S_/2; i += 256){
        float2 v = __bfloat1622float2(row2[i]);
        float2 l = li2[i];
        acc += v.x*l.x + v.y*l.y;
    }
    __shared__ float red[256];
    red[tid] = acc; __syncthreads();
    for (int st = 128; st > 0; st >>= 1){
        if (tid < st) red[tid] += red[tid + st];
        __syncthreads();
    }
    if (tid == 0) r[(long long)b*S_ + s] = red[0];
}

// ---------------- out = tanh(r * VL + bl) -----------------------------------
__global__ void out_kernel(const float* __restrict__ VL, const float* __restrict__ r,
                           const float* __restrict__ bl, float* __restrict__ out){
    long long i = (long long)blockIdx.x*256 + threadIdx.x;
    float4 v = ((const float4*)VL)[i];
    float rv = r[i >> 7];
    float4 b4 = ((const float4*)bl)[(int)(i & 127)];
    float4 o;
    o.x = tanhf(rv*v.x + b4.x);
    o.y = tanhf(rv*v.y + b4.y);
    o.z = tanhf(rv*v.z + b4.z);
    o.w = tanhf(rv*v.w + b4.w);
    ((float4*)out)[i] = o;
}

// ---------------- launcher --------------------------------------------------
extern "C" void kernel_launch(void* const* d_in, const int* in_sizes, int n_in,
                              void* d_out, int out_size){
    const float* xs = (const float*)d_in[0];
    const float* Wk = (const float*)d_in[1];
    const float* bk = (const float*)d_in[2];
    const float* Wq = (const float*)d_in[3];
    const float* bq = (const float*)d_in[4];
    const float* Wv = (const float*)d_in[5];
    const float* bv = (const float*)d_in[6];
    const float* Wl = (const float*)d_in[7];
    const float* bl = (const float*)d_in[8];
    float* out = (float*)d_out;
    (void)in_sizes; (void)n_in; (void)out_size;

    float *pVL, *pPart, *pLinv, *pR, *pWc, *pBc;
    __nv_bfloat16 *pXh, *pWkh, *pWqh, *pKh, *pQh, *pE;
    cudaGetSymbolAddress((void**)&pXh,   g_Xh);
    cudaGetSymbolAddress((void**)&pWkh,  g_Wkh);
    cudaGetSymbolAddress((void**)&pWqh,  g_Wqh);
    cudaGetSymbolAddress((void**)&pKh,   g_Kh);
    cudaGetSymbolAddress((void**)&pQh,   g_Qh);
    cudaGetSymbolAddress((void**)&pVL,   g_VL);
    cudaGetSymbolAddress((void**)&pE,    g_E);
    cudaGetSymbolAddress((void**)&pPart, g_part);
    cudaGetSymbolAddress((void**)&pLinv, g_Linv);
    cudaGetSymbolAddress((void**)&pR,    g_r);
    cudaGetSymbolAddress((void**)&pWc,   g_Wc);
    cudaGetSymbolAddress((void**)&pBc,   g_bc);

    // 0) bf16 casts                                             (launch 0,1,2)
    cvt_bf16<<<(M1*D_/8)/256, 256>>>((const float4*)xs, (uint4*)pXh);
    cvt_bf16<<<(D_*D_/8)/256, 256>>>((const float4*)Wk, (uint4*)pWkh);
    cvt_bf16<<<(D_*D_/8)/256, 256>>>((const float4*)Wq, (uint4*)pWqh);

    // 1) combined last-layer weights                            (launch 3,4)
    wc_gemm<<<dim3(D_/64, D_/64), 256>>>(Wl, Wv, pWc);
    bc_kernel<<<D_, 128>>>(Wl, bv, pBc);

    // 2) K, Q in bf16 HMMA                                      (launch 5 -> ncu, 6)
    gemm_bf16<1><<<dim3(D_/BNT, M1/BMT), 256>>>(pXh, pWkh, bk, pKh, M1, D_, D_, 0, 0, 0);
    gemm_bf16<1><<<dim3(D_/BNT, M1/BMT), 256>>>(pXh, pWqh, bq, pQh, M1, D_, D_, 0, 0, 0);

    // 3) VL in tf32 (accuracy-critical output path)             (launch 7)
    gemm_tf32<<<dim3(D_/BNT, M1/BMT), 256>>>(xs, pWc, pBc, pVL, M1, D_, D_);

    // 4) E[b] = exp((K@Q^T)/512) in bf16 HMMA, batched          (launch 8)
    gemm_bf16<2><<<dim3(S_/BNT, S_/BMT, B_), 256>>>(pKh, pQh, nullptr, pE,
                                                    S_, S_, D_,
                                                    (long long)S_*D_, (long long)S_*D_,
                                                    (long long)S_*S_);

    // 5) Linv, r
    colsum_part<<<dim3(S_/256, 8, B_), 256>>>(pE, pPart);
    linv_kernel<<<(B_*S_)/256, 256>>>(pPart, pLinv);
    rowsum_kernel<<<dim3(S_, B_), 256>>>(pE, pLinv, pR);

    // 6) out = tanh(r * VL + bl)
    out_kernel<<<(B_*S_*D_/4)/256, 256>>>(pVL, pR, bl, out);
}

// round 13
// speedup vs baseline: 1.6908x; 1.1337x over previous
#include <cuda_runtime.h>
#include <cuda_bf16.h>
#include <cstdint>

#define B_ 4
#define S_ 4096
#define D_ 512
#define M1 (B_*S_)   // 16384

// ---------------- scratch (device globals: the sanctioned no-alloc path) ----
__device__ __nv_bfloat16 g_Xh [M1*D_];               // bf16 xs
__device__ __nv_bfloat16 g_Wkh[D_*D_];               // bf16 Wk
__device__ __nv_bfloat16 g_Wqh[D_*D_];               // bf16 Wq
__device__ __nv_bfloat16 g_Kh [B_*S_*D_];            // bf16 K
__device__ __nv_bfloat16 g_Qh [B_*S_*D_];            // bf16 Q
__device__ float         g_VL [B_*S_*D_];
__device__ __nv_bfloat16 g_E  [(size_t)B_*S_*S_];    // E[b][s][e] = exp(qk/512)
__device__ float         g_part[B_*32*S_];           // per-m-tile column sums
__device__ float         g_Linv[B_*S_];
__device__ float         g_r  [B_*S_];
__device__ float         g_WcP[2*D_*D_];             // split-K partials
__device__ float         g_Wc [D_*D_];
__device__ float         g_bc [D_];

// ---------------- helpers ---------------------------------------------------
__device__ __forceinline__ uint32_t f2tf(float x){
    uint32_t r; asm("cvt.rna.tf32.f32 %0, %1;" : "=r"(r) : "f"(x)); return r;
}
__device__ __forceinline__ void mma_tf(float c[4], const uint32_t a[4], const uint32_t b[2]){
    asm volatile(
        "mma.sync.aligned.m16n8k8.row.col.f32.tf32.tf32.f32 "
        "{%0,%1,%2,%3}, {%4,%5,%6,%7}, {%8,%9}, {%0,%1,%2,%3};"
        : "+f"(c[0]), "+f"(c[1]), "+f"(c[2]), "+f"(c[3])
        : "r"(a[0]), "r"(a[1]), "r"(a[2]), "r"(a[3]), "r"(b[0]), "r"(b[1]));
}
__device__ __forceinline__ void mma_bf(float c[4], const uint32_t a[4], const uint32_t b[2]){
    asm volatile(
        "mma.sync.aligned.m16n8k16.row.col.f32.bf16.bf16.f32 "
        "{%0,%1,%2,%3}, {%4,%5,%6,%7}, {%8,%9}, {%0,%1,%2,%3};"
        : "+f"(c[0]), "+f"(c[1]), "+f"(c[2]), "+f"(c[3])
        : "r"(a[0]), "r"(a[1]), "r"(a[2]), "r"(a[3]), "r"(b[0]), "r"(b[1]));
}

// ---------------- float -> bf16 cast (8 elems/thread) ------------------------
__global__ void cvt_bf16(const float4* __restrict__ src, uint4* __restrict__ dst){
    int i = blockIdx.x*256 + threadIdx.x;
    float4 a = src[2*i], b = src[2*i+1];
    __nv_bfloat162 p0 = __floats2bfloat162_rn(a.x, a.y);
    __nv_bfloat162 p1 = __floats2bfloat162_rn(a.z, a.w);
    __nv_bfloat162 p2 = __floats2bfloat162_rn(b.x, b.y);
    __nv_bfloat162 p3 = __floats2bfloat162_rn(b.z, b.w);
    uint4 q;
    q.x = *(uint32_t*)&p0; q.y = *(uint32_t*)&p1;
    q.z = *(uint32_t*)&p2; q.w = *(uint32_t*)&p3;
    dst[i] = q;
}

// ---------------- Wc = Wl @ Wv: split-K x2, reg-prefetched -------------------
__global__ void __launch_bounds__(256)
wc_gemm(const float* __restrict__ Wl, const float* __restrict__ Wv,
        float* __restrict__ WcP){
    __shared__ float sL[16][65];
    __shared__ float sV[16][65];
    const int bj = blockIdx.y*64, bi = blockIdx.x*64;
    const int z  = blockIdx.z;           // K half
    const int kbase = z*256;
    const int tx = threadIdx.x & 15, ty = threadIdx.x >> 4;

    float acc[4][4];
    #pragma unroll
    for (int m = 0; m < 4; m++)
        #pragma unroll
        for (int n = 0; n < 4; n++) acc[m][n] = 0.f;

    // per-thread staging coords
    int rL[4], cL[4], rV[4], cV[4];
    #pragma unroll
    for (int p = 0; p < 4; p++){
        int idx = threadIdx.x + p*256;
        rL[p] = idx >> 4; cL[p] = idx & 15;
        rV[p] = idx >> 6; cV[p] = idx & 63;
    }

    float ra[4], rb[4];
    #pragma unroll
    for (int p = 0; p < 4; p++){
        ra[p] = Wl[(bj + rL[p])*D_ + kbase + cL[p]];
        rb[p] = Wv[(kbase + rV[p])*D_ + bi + cV[p]];
    }

    for (int it = 0; it < 16; it++){
        #pragma unroll
        for (int p = 0; p < 4; p++){
            sL[cL[p]][rL[p]] = ra[p];
            sV[rV[p]][cV[p]] = rb[p];
        }
        __syncthreads();
        if (it < 15){
            int k0 = kbase + (it + 1)*16;
            #pragma unroll
            for (int p = 0; p < 4; p++){
                ra[p] = Wl[(bj + rL[p])*D_ + k0 + cL[p]];
                rb[p] = Wv[(k0 + rV[p])*D_ + bi + cV[p]];
            }
        }
        #pragma unroll
        for (int k = 0; k < 16; k++){
            float a[4], b[4];
            #pragma unroll
            for (int m = 0; m < 4; m++) a[m] = sL[k][ty*4 + m];
            #pragma unroll
            for (int n = 0; n < 4; n++) b[n] = sV[k][tx*4 + n];
            #pragma unroll
            for (int m = 0; m < 4; m++)
                #pragma unroll
                for (int n = 0; n < 4; n++) acc[m][n] += a[m]*b[n];
        }
        __syncthreads();
    }
    #pragma unroll
    for (int m = 0; m < 4; m++)
        #pragma unroll
        for (int n = 0; n < 4; n++)
            WcP[(size_t)z*D_*D_ + (bj + ty*4 + m)*D_ + bi + tx*4 + n] = acc[m][n];
}

__global__ void wc_reduce(const float4* __restrict__ P, float4* __restrict__ Wc){
    int i = blockIdx.x*256 + threadIdx.x;
    float4 a = P[i], b = P[i + D_*D_/4];
    Wc[i] = make_float4(a.x+b.x, a.y+b.y, a.z+b.z, a.w+b.w);
}

// ---------------- bc = Wl @ bv ----------------------------------------------
__global__ void bc_kernel(const float* __restrict__ Wl, const float* __restrict__ bv,
                          float* __restrict__ bc){
    int j = blockIdx.x;
    __shared__ float red[128];
    float a = 0.f;
    for (int k = threadIdx.x; k < D_; k += 128) a += Wl[j*D_ + k]*bv[k];
    red[threadIdx.x] = a; __syncthreads();
    for (int s = 64; s > 0; s >>= 1){
        if (threadIdx.x < s) red[threadIdx.x] += red[threadIdx.x + s];
        __syncthreads();
    }
    if (threadIdx.x == 0) bc[j] = red[0];
}

// ---------------- tf32 mma GEMM (VL path only): Cf = A @ B^T + bias ---------
#define BMT 128
#define BNT 128
#define LDT 36   // u32 row pitch with +4 pad: conflict-free LDS/STS

__global__ void __launch_bounds__(256, 2)
gemm_tf32(const float* __restrict__ Ag, const float* __restrict__ Bg,
          const float* __restrict__ bias, float* __restrict__ Cf,
          int M, int N, int K)
{
    __shared__ __align__(16) uint32_t sA[BMT*LDT];
    __shared__ __align__(16) uint32_t sB[BNT*LDT];

    const int tid  = threadIdx.x;
    const int bm = blockIdx.y*BMT, bn = blockIdx.x*BNT;
    const int lane = tid & 31, warp = tid >> 5;
    const int wm = (warp & 1)*64, wn = (warp >> 1)*32;
    const int g = lane >> 2, t = lane & 3;
    const int lrow = tid >> 3, lcol = (tid & 7)*4;

    float acc[4][4][4];
    #pragma unroll
    for (int i = 0; i < 4; i++)
        #pragma unroll
        for (int j = 0; j < 4; j++)
            #pragma unroll
            for (int c = 0; c < 4; c++) acc[i][j][c] = 0.f;

    for (int k0 = 0; k0 < K; k0 += 32){
        #pragma unroll
        for (int p = 0; p < 4; p++){
            int r = lrow + p*32;
            float4 va = *(const float4*)(Ag + (long long)(bm + r)*K + k0 + lcol);
            *(uint4*)&sA[r*LDT + lcol] = make_uint4(f2tf(va.x), f2tf(va.y), f2tf(va.z), f2tf(va.w));
            float4 vb = *(const float4*)(Bg + (long long)(bn + r)*K + k0 + lcol);
            *(uint4*)&sB[r*LDT + lcol] = make_uint4(f2tf(vb.x), f2tf(vb.y), f2tf(vb.z), f2tf(vb.w));
        }
        __syncthreads();
        #pragma unroll
        for (int kk = 0; kk < 32; kk += 8){
            uint32_t af[4][4], bf[4][2];
            #pragma unroll
            for (int mi = 0; mi < 4; mi++){
                int r = wm + mi*16 + g;
                af[mi][0] = sA[ r    *LDT + kk + t    ];
                af[mi][1] = sA[(r+8) *LDT + kk + t    ];
                af[mi][2] = sA[ r    *LDT + kk + t + 4];
                af[mi][3] = sA[(r+8) *LDT + kk + t + 4];
            }
            #pragma unroll
            for (int ni = 0; ni < 4; ni++){
                int rn = wn + ni*8 + g;
                bf[ni][0] = sB[rn*LDT + kk + t    ];
                bf[ni][1] = sB[rn*LDT + kk + t + 4];
            }
            #pragma unroll
            for (int mi = 0; mi < 4; mi++)
                #pragma unroll
                for (int ni = 0; ni < 4; ni++)
                    mma_tf(acc[mi][ni], af[mi], bf[ni]);
        }
        __syncthreads();
    }

    #pragma unroll
    for (int mi = 0; mi < 4; mi++){
        int r0 = bm + wm + mi*16 + g;
        #pragma unroll
        for (int ni = 0; ni < 4; ni++){
            int c = bn + wn + ni*8 + 2*t;
            float* ac = acc[mi][ni];
            float b0 = bias[c], b1 = bias[c+1];
            *(float2*)(Cf + (long long)r0*N + c)     = make_float2(ac[0]+b0, ac[1]+b1);
            *(float2*)(Cf + (long long)(r0+8)*N + c) = make_float2(ac[2]+b0, ac[3]+b1);
        }
    }
}

// ---------------- bf16 m16n8k16 GEMM, reg double-buffered -------------------
// A: [M,K] bf16 rm, B: [N,K] bf16 rm. BK=64 bf16 (32 u32 cols, pitch LDT=36).
// EPI 1: Cb = bf16(acc + bias)                      (K, Q)
// EPI 2: Cb = bf16(exp(acc/512)) + fused column-sum partials (E)
template<int EPI>
__global__ void __launch_bounds__(256)
gemm_bf16(const __nv_bfloat16* __restrict__ Ag, const __nv_bfloat16* __restrict__ Bg,
          const float* __restrict__ bias, __nv_bfloat16* __restrict__ Cb,
          float* __restrict__ part,
          int M, int N, int K,
          long long strA, long long strB, long long strC)
{
    __shared__ __align__(16) uint32_t sA[BMT*LDT];
    __shared__ __align__(16) uint32_t sB[BNT*LDT];
    __shared__ float cpart[2][128];

    const int tid  = threadIdx.x;
    const long long bz = blockIdx.z;
    const int bm = blockIdx.y*BMT, bn = blockIdx.x*BNT;
    const int lane = tid & 31, warp = tid >> 5;
    const int wm = (warp & 1)*64, wn = (warp >> 1)*32;
    const int g = lane >> 2, t = lane & 3;
    const int lrow = tid >> 1;                 // 0..127 (staging row)
    const int lch  = (tid & 1)*4;              // 2 threads/row, 4 16B-chunks each

    const __nv_bfloat16* aptr = Ag + bz*strA + (long long)(bm + lrow)*K + lch*8;
    const __nv_bfloat16* bptr = Bg + bz*strB + (long long)(bn + lrow)*K + lch*8;

    float acc[4][4][4];
    #pragma unroll
    for (int i = 0; i < 4; i++)
        #pragma unroll
        for (int j = 0; j < 4; j++)
            #pragma unroll
            for (int c = 0; c < 4; c++) acc[i][j][c] = 0.f;

    // prologue: prefetch tile 0 into registers
    uint4 pa[4], pb[4];
    #pragma unroll
    for (int c = 0; c < 4; c++){
        pa[c] = *(const uint4*)(aptr + c*8);
        pb[c] = *(const uint4*)(bptr + c*8);
    }

    for (int k0 = 0; k0 < K; k0 += 64){
        #pragma unroll
        for (int c = 0; c < 4; c++){
            *(uint4*)&sA[lrow*LDT + (lch + c)*4] = pa[c];
            *(uint4*)&sB[lrow*LDT + (lch + c)*4] = pb[c];
        }
        __syncthreads();
        if (k0 + 64 < K){
            #pragma unroll
            for (int c = 0; c < 4; c++){
                pa[c] = *(const uint4*)(aptr + k0 + 64 + c*8);
                pb[c] = *(const uint4*)(bptr + k0 + 64 + c*8);
            }
        }
        #pragma unroll
        for (int kk = 0; kk < 32; kk += 8){    // each kk = one k16 step
            uint32_t af[4][4], bf[4][2];
            #pragma unroll
            for (int mi = 0; mi < 4; mi++){
                int r = wm + mi*16 + g;
                af[mi][0] = sA[ r    *LDT + kk + t    ];
                af[mi][1] = sA[(r+8) *LDT + kk + t    ];
                af[mi][2] = sA[ r    *LDT + kk + t + 4];
                af[mi][3] = sA[(r+8) *LDT + kk + t + 4];
            }
            #pragma unroll
            for (int ni = 0; ni < 4; ni++){
                int rn = wn + ni*8 + g;
                bf[ni][0] = sB[rn*LDT + kk + t    ];
                bf[ni][1] = sB[rn*LDT + kk + t + 4];
            }
            #pragma unroll
            for (int mi = 0; mi < 4; mi++)
                #pragma unroll
                for (int ni = 0; ni < 4; ni++)
                    mma_bf(acc[mi][ni], af[mi], bf[ni]);
        }
        __syncthreads();
    }

    __nv_bfloat16* Co = Cb + bz*strC;
    if (EPI == 1){
        #pragma unroll
        for (int mi = 0; mi < 4; mi++){
            int r0 = bm + wm + mi*16 + g;
            #pragma unroll
            for (int ni = 0; ni < 4; ni++){
                int c = bn + wn + ni*8 + 2*t;
                float* ac = acc[mi][ni];
                float b0 = bias[c], b1 = bias[c+1];
                *(__nv_bfloat162*)(Co + (long long)r0*N + c) =
                    __floats2bfloat162_rn(ac[0]+b0, ac[1]+b1);
                *(__nv_bfloat162*)(Co + (long long)(r0+8)*N + c) =
                    __floats2bfloat162_rn(ac[2]+b0, ac[3]+b1);
            }
        }
    } else {
        const float inv = 1.0f/512.0f;
        float csum[4][2];
        #pragma unroll
        for (int ni = 0; ni < 4; ni++){ csum[ni][0] = 0.f; csum[ni][1] = 0.f; }

        #pragma unroll
        for (int mi = 0; mi < 4; mi++){
            int r0 = bm + wm + mi*16 + g;
            #pragma unroll
            for (int ni = 0; ni < 4; ni++){
                int c = bn + wn + ni*8 + 2*t;
                float* ac = acc[mi][ni];
                float e0 = __expf(ac[0]*inv), e1 = __expf(ac[1]*inv);
                float e2 = __expf(ac[2]*inv), e3 = __expf(ac[3]*inv);
                *(__nv_bfloat162*)(Co + (long long)r0*N + c)     = __floats2bfloat162_rn(e0, e1);
                *(__nv_bfloat162*)(Co + (long long)(r0+8)*N + c) = __floats2bfloat162_rn(e2, e3);
                csum[ni][0] += e0 + e2;
                csum[ni][1] += e1 + e3;
            }
        }
        // reduce over g (lane bits 2..4): lanes with same t share a column
        #pragma unroll
        for (int m = 4; m <= 16; m <<= 1)
            #pragma unroll
            for (int ni = 0; ni < 4; ni++){
                csum[ni][0] += __shfl_xor_sync(0xffffffffu, csum[ni][0], m);
                csum[ni][1] += __shfl_xor_sync(0xffffffffu, csum[ni][1], m);
            }
        if (lane < 4){   // g == 0; lane == t
            #pragma unroll
            for (int ni = 0; ni < 4; ni++){
                cpart[warp & 1][wn + ni*8 + 2*lane    ] = csum[ni][0];
                cpart[warp & 1][wn + ni*8 + 2*lane + 1] = csum[ni][1];
            }
        }
        __syncthreads();
        if (tid < 128){
            float v = cpart[0][tid] + cpart[1][tid];
            part[((bz*32 + blockIdx.y)*(long long)S_) + bn + tid] = v;
        }
    }
}

// ---------------- Linv from 32 per-tile partials ----------------------------
__global__ void linv_kernel(const float* __restrict__ part, float* __restrict__ Linv){
    int i = blockIdx.x*256 + threadIdx.x;          // b*S + e
    int b = i >> 12, e = i & (S_-1);
    float s = 0.f;
    #pragma unroll
    for (int c = 0; c < 32; c++) s += part[(b*32 + c)*(long long)S_ + e];
    Linv[i] = 1.0f / s;
}

// ---------------- row-sum of E * Linv ---------------------------------------
__global__ void rowsum_kernel(const __nv_bfloat16* __restrict__ E,
                              const float* __restrict__ Linv, float* __restrict__ r){
    int s = blockIdx.x, b = blockIdx.y, tid = threadIdx.x;
    const __nv_bfloat162* row2 = (const __nv_bfloat162*)(E + ((long long)b*S_ + s)*S_);
    const float2* li2 = (const float2*)(Linv + b*S_);
    float acc = 0.f;
    #pragma unroll 4
    for (int i = tid; i < S_/2; i += 256){
        float2 v = __bfloat1622float2(row2[i]);
        float2 l = li2[i];
        acc += v.x*l.x + v.y*l.y;
    }
    __shared__ float red[256];
    red[tid] = acc; __syncthreads();
    for (int st = 128; st > 0; st >>= 1){
        if (tid < st) red[tid] += red[tid + st];
        __syncthreads();
    }
    if (tid == 0) r[(long long)b*S_ + s] = red[0];
}

// ---------------- out = tanh(r * VL + bl) -----------------------------------
__global__ void out_kernel(const float* __restrict__ VL, const float* __restrict__ r,
                           const float* __restrict__ bl, float* __restrict__ out){
    long long i = (long long)blockIdx.x*256 + threadIdx.x;
    float4 v = ((const float4*)VL)[i];
    float rv = r[i >> 7];
    float4 b4 = ((const float4*)bl)[(int)(i & 127)];
    float4 o;
    o.x = tanhf(rv*v.x + b4.x);
    o.y = tanhf(rv*v.y + b4.y);
    o.z = tanhf(rv*v.z + b4.z);
    o.w = tanhf(rv*v.w + b4.w);
    ((float4*)out)[i] = o;
}

// ---------------- launcher --------------------------------------------------
extern "C" void kernel_launch(void* const* d_in, const int* in_sizes, int n_in,
                              void* d_out, int out_size){
    const float* xs = (const float*)d_in[0];
    const float* Wk = (const float*)d_in[1];
    const float* bk = (const float*)d_in[2];
    const float* Wq = (const float*)d_in[3];
    const float* bq = (const float*)d_in[4];
    const float* Wv = (const float*)d_in[5];
    const float* bv = (const float*)d_in[6];
    const float* Wl = (const float*)d_in[7];
    const float* bl = (const float*)d_in[8];
    float* out = (float*)d_out;
    (void)in_sizes; (void)n_in; (void)out_size;

    float *pVL, *pPart, *pLinv, *pR, *pWcP, *pWc, *pBc;
    __nv_bfloat16 *pXh, *pWkh, *pWqh, *pKh, *pQh, *pE;
    cudaGetSymbolAddress((void**)&pXh,   g_Xh);
    cudaGetSymbolAddress((void**)&pWkh,  g_Wkh);
    cudaGetSymbolAddress((void**)&pWqh,  g_Wqh);
    cudaGetSymbolAddress((void**)&pKh,   g_Kh);
    cudaGetSymbolAddress((void**)&pQh,   g_Qh);
    cudaGetSymbolAddress((void**)&pVL,   g_VL);
    cudaGetSymbolAddress((void**)&pE,    g_E);
    cudaGetSymbolAddress((void**)&pPart, g_part);
    cudaGetSymbolAddress((void**)&pLinv, g_Linv);
    cudaGetSymbolAddress((void**)&pR,    g_r);
    cudaGetSymbolAddress((void**)&pWcP,  g_WcP);
    cudaGetSymbolAddress((void**)&pWc,   g_Wc);
    cudaGetSymbolAddress((void**)&pBc,   g_bc);

    // 0) bf16 casts
    cvt_bf16<<<(M1*D_/8)/256, 256>>>((const float4*)xs, (uint4*)pXh);
    cvt_bf16<<<(D_*D_/8)/256, 256>>>((const float4*)Wk, (uint4*)pWkh);
    cvt_bf16<<<(D_*D_/8)/256, 256>>>((const float4*)Wq, (uint4*)pWqh);

    // 1) combined last-layer weights: Wc = Wl@Wv (split-K2), bc = Wl@bv
    wc_gemm<<<dim3(D_/64, D_/64, 2), 256>>>(Wl, Wv, pWcP);
    wc_reduce<<<(D_*D_/4)/256, 256>>>((const float4*)pWcP, (float4*)pWc);
    bc_kernel<<<D_, 128>>>(Wl, bv, pBc);

    // 2) K, Q in bf16 HMMA (reg double-buffered)
    gemm_bf16<1><<<dim3(D_/BNT, M1/BMT), 256>>>(pXh, pWkh, bk, pKh, nullptr,
                                                M1, D_, D_, 0, 0, 0);
    gemm_bf16<1><<<dim3(D_/BNT, M1/BMT), 256>>>(pXh, pWqh, bq, pQh, nullptr,
                                                M1, D_, D_, 0, 0, 0);

    // 3) VL in tf32 (accuracy-critical output path)
    gemm_tf32<<<dim3(D_/BNT, M1/BMT), 256>>>(xs, pWc, pBc, pVL, M1, D_, D_);

    // 4) E[b] = exp((K@Q^T)/512), fused column-sum partials
    gemm_bf16<2><<<dim3(S_/BNT, S_/BMT, B_), 256>>>(pKh, pQh, nullptr, pE, pPart,
                                                    S_, S_, D_,
                                                    (long long)S_*D_, (long long)S_*D_,
                                                    (long long)S_*S_);

    // 5) Linv, r
    linv_kernel<<<(B_*S_)/256, 256>>>(pPart, pLinv);
    rowsum_kernel<<<dim3(S_, B_), 256>>>(pE, pLinv, pR);

    // 6) out = tanh(r * VL + bl)
    out_kernel<<<(B_*S_*D_/4)/256, 256>>>(pVL, pR, bl, out);
}

// round 14
// speedup vs baseline: 1.7388x; 1.0284x over previous
#include <cuda_runtime.h>
#include <cuda_bf16.h>
#include <cstdint>

#define B_ 4
#define S_ 4096
#define D_ 512
#define M1 (B_*S_)   // 16384

// ---------------- scratch (device globals: the sanctioned no-alloc path) ----
__device__ __nv_bfloat16 g_Xh [M1*D_];               // bf16 xs
__device__ __nv_bfloat16 g_Wkh[D_*D_];               // bf16 Wk
__device__ __nv_bfloat16 g_Wqh[D_*D_];               // bf16 Wq
__device__ __nv_bfloat16 g_Kh [B_*S_*D_];            // bf16 K
__device__ __nv_bfloat16 g_Qh [B_*S_*D_];            // bf16 Q
__device__ float         g_VL [B_*S_*D_];
__device__ __nv_bfloat16 g_E  [(size_t)B_*S_*S_];    // E[b][s][e] = exp(qk/512)
__device__ float         g_part[B_*32*S_];           // per-m-tile column sums
__device__ float         g_Linv[B_*S_];
__device__ float         g_r  [B_*S_];
__device__ float         g_WcP[2*D_*D_];             // split-K partials
__device__ float         g_Wc [D_*D_];
__device__ float         g_bc [D_];

// ---------------- helpers ---------------------------------------------------
__device__ __forceinline__ uint32_t f2tf(float x){
    uint32_t r; asm("cvt.rna.tf32.f32 %0, %1;" : "=r"(r) : "f"(x)); return r;
}
__device__ __forceinline__ void mma_tf(float c[4], const uint32_t a[4], const uint32_t b[2]){
    asm volatile(
        "mma.sync.aligned.m16n8k8.row.col.f32.tf32.tf32.f32 "
        "{%0,%1,%2,%3}, {%4,%5,%6,%7}, {%8,%9}, {%0,%1,%2,%3};"
        : "+f"(c[0]), "+f"(c[1]), "+f"(c[2]), "+f"(c[3])
        : "r"(a[0]), "r"(a[1]), "r"(a[2]), "r"(a[3]), "r"(b[0]), "r"(b[1]));
}
__device__ __forceinline__ void mma_bf(float c[4], const uint32_t a[4], const uint32_t b[2]){
    asm volatile(
        "mma.sync.aligned.m16n8k16.row.col.f32.bf16.bf16.f32 "
        "{%0,%1,%2,%3}, {%4,%5,%6,%7}, {%8,%9}, {%0,%1,%2,%3};"
        : "+f"(c[0]), "+f"(c[1]), "+f"(c[2]), "+f"(c[3])
        : "r"(a[0]), "r"(a[1]), "r"(a[2]), "r"(a[3]), "r"(b[0]), "r"(b[1]));
}

// ---------------- float -> bf16 cast (8 elems/thread) ------------------------
__global__ void cvt_bf16(const float4* __restrict__ src, uint4* __restrict__ dst){
    int i = blockIdx.x*256 + threadIdx.x;
    float4 a = src[2*i], b = src[2*i+1];
    __nv_bfloat162 p0 = __floats2bfloat162_rn(a.x, a.y);
    __nv_bfloat162 p1 = __floats2bfloat162_rn(a.z, a.w);
    __nv_bfloat162 p2 = __floats2bfloat162_rn(b.x, b.y);
    __nv_bfloat162 p3 = __floats2bfloat162_rn(b.z, b.w);
    uint4 q;
    q.x = *(uint32_t*)&p0; q.y = *(uint32_t*)&p1;
    q.z = *(uint32_t*)&p2; q.w = *(uint32_t*)&p3;
    dst[i] = q;
}

// ---------------- Wc = Wl @ Wv: split-K x2, reg-prefetched -------------------
__global__ void __launch_bounds__(256)
wc_gemm(const float* __restrict__ Wl, const float* __restrict__ Wv,
        float* __restrict__ WcP){
    __shared__ float sL[16][65];
    __shared__ float sV[16][65];
    const int bj = blockIdx.y*64, bi = blockIdx.x*64;
    const int z  = blockIdx.z;           // K half
    const int kbase = z*256;
    const int tx = threadIdx.x & 15, ty = threadIdx.x >> 4;

    float acc[4][4];
    #pragma unroll
    for (int m = 0; m < 4; m++)
        #pragma unroll
        for (int n = 0; n < 4; n++) acc[m][n] = 0.f;

    int rL[4], cL[4], rV[4], cV[4];
    #pragma unroll
    for (int p = 0; p < 4; p++){
        int idx = threadIdx.x + p*256;
        rL[p] = idx >> 4; cL[p] = idx & 15;
        rV[p] = idx >> 6; cV[p] = idx & 63;
    }

    float ra[4], rb[4];
    #pragma unroll
    for (int p = 0; p < 4; p++){
        ra[p] = Wl[(bj + rL[p])*D_ + kbase + cL[p]];
        rb[p] = Wv[(kbase + rV[p])*D_ + bi + cV[p]];
    }

    for (int it = 0; it < 16; it++){
        #pragma unroll
        for (int p = 0; p < 4; p++){
            sL[cL[p]][rL[p]] = ra[p];
            sV[rV[p]][cV[p]] = rb[p];
        }
        __syncthreads();
        if (it < 15){
            int k0 = kbase + (it + 1)*16;
            #pragma unroll
            for (int p = 0; p < 4; p++){
                ra[p] = Wl[(bj + rL[p])*D_ + k0 + cL[p]];
                rb[p] = Wv[(k0 + rV[p])*D_ + bi + cV[p]];
            }
        }
        #pragma unroll
        for (int k = 0; k < 16; k++){
            float a[4], b[4];
            #pragma unroll
            for (int m = 0; m < 4; m++) a[m] = sL[k][ty*4 + m];
            #pragma unroll
            for (int n = 0; n < 4; n++) b[n] = sV[k][tx*4 + n];
            #pragma unroll
            for (int m = 0; m < 4; m++)
                #pragma unroll
                for (int n = 0; n < 4; n++) acc[m][n] += a[m]*b[n];
        }
        __syncthreads();
    }
    #pragma unroll
    for (int m = 0; m < 4; m++)
        #pragma unroll
        for (int n = 0; n < 4; n++)
            WcP[(size_t)z*D_*D_ + (bj + ty*4 + m)*D_ + bi + tx*4 + n] = acc[m][n];
}

__global__ void wc_reduce(const float4* __restrict__ P, float4* __restrict__ Wc){
    int i = blockIdx.x*256 + threadIdx.x;
    float4 a = P[i], b = P[i + D_*D_/4];
    Wc[i] = make_float4(a.x+b.x, a.y+b.y, a.z+b.z, a.w+b.w);
}

// ---------------- bc = Wl @ bv ----------------------------------------------
__global__ void bc_kernel(const float* __restrict__ Wl, const float* __restrict__ bv,
                          float* __restrict__ bc){
    int j = blockIdx.x;
    __shared__ float red[128];
    float a = 0.f;
    for (int k = threadIdx.x; k < D_; k += 128) a += Wl[j*D_ + k]*bv[k];
    red[threadIdx.x] = a; __syncthreads();
    for (int s = 64; s > 0; s >>= 1){
        if (threadIdx.x < s) red[threadIdx.x] += red[threadIdx.x + s];
        __syncthreads();
    }
    if (threadIdx.x == 0) bc[j] = red[0];
}

// ---------------- tf32 mma GEMM (VL path): Cf = A @ B^T + bias --------------
// A-rows prefetched in registers (B is small & L2-resident, loaded in-loop).
#define BMT 128
#define BNT 128
#define LDT 36   // u32 row pitch with +4 pad: conflict-free LDS/STS

__global__ void __launch_bounds__(256, 2)
gemm_tf32(const float* __restrict__ Ag, const float* __restrict__ Bg,
          const float* __restrict__ bias, float* __restrict__ Cf,
          int M, int N, int K)
{
    __shared__ __align__(16) uint32_t sA[BMT*LDT];
    __shared__ __align__(16) uint32_t sB[BNT*LDT];

    const int tid  = threadIdx.x;
    const int bm = blockIdx.y*BMT, bn = blockIdx.x*BNT;
    const int lane = tid & 31, warp = tid >> 5;
    const int wm = (warp & 1)*64, wn = (warp >> 1)*32;
    const int g = lane >> 2, t = lane & 3;
    const int lrow = tid >> 3, lcol = (tid & 7)*4;

    float acc[4][4][4];
    #pragma unroll
    for (int i = 0; i < 4; i++)
        #pragma unroll
        for (int j = 0; j < 4; j++)
            #pragma unroll
            for (int c = 0; c < 4; c++) acc[i][j][c] = 0.f;

    // prefetch A tile 0
    float4 pa[4];
    #pragma unroll
    for (int p = 0; p < 4; p++)
        pa[p] = *(const float4*)(Ag + (long long)(bm + lrow + p*32)*K + lcol);

    for (int k0 = 0; k0 < K; k0 += 32){
        #pragma unroll
        for (int p = 0; p < 4; p++){
            int r = lrow + p*32;
            *(uint4*)&sA[r*LDT + lcol] =
                make_uint4(f2tf(pa[p].x), f2tf(pa[p].y), f2tf(pa[p].z), f2tf(pa[p].w));
            float4 vb = *(const float4*)(Bg + (long long)(bn + r)*K + k0 + lcol);
            *(uint4*)&sB[r*LDT + lcol] = make_uint4(f2tf(vb.x), f2tf(vb.y), f2tf(vb.z), f2tf(vb.w));
        }
        __syncthreads();
        if (k0 + 32 < K){
            #pragma unroll
            for (int p = 0; p < 4; p++)
                pa[p] = *(const float4*)(Ag + (long long)(bm + lrow + p*32)*K + k0 + 32 + lcol);
        }
        #pragma unroll
        for (int kk = 0; kk < 32; kk += 8){
            uint32_t af[4][4], bf[4][2];
            #pragma unroll
            for (int mi = 0; mi < 4; mi++){
                int r = wm + mi*16 + g;
                af[mi][0] = sA[ r    *LDT + kk + t    ];
                af[mi][1] = sA[(r+8) *LDT + kk + t    ];
                af[mi][2] = sA[ r    *LDT + kk + t + 4];
                af[mi][3] = sA[(r+8) *LDT + kk + t + 4];
            }
            #pragma unroll
            for (int ni = 0; ni < 4; ni++){
                int rn = wn + ni*8 + g;
                bf[ni][0] = sB[rn*LDT + kk + t    ];
                bf[ni][1] = sB[rn*LDT + kk + t + 4];
            }
            #pragma unroll
            for (int mi = 0; mi < 4; mi++)
                #pragma unroll
                for (int ni = 0; ni < 4; ni++)
                    mma_tf(acc[mi][ni], af[mi], bf[ni]);
        }
        __syncthreads();
    }

    #pragma unroll
    for (int mi = 0; mi < 4; mi++){
        int r0 = bm + wm + mi*16 + g;
        #pragma unroll
        for (int ni = 0; ni < 4; ni++){
            int c = bn + wn + ni*8 + 2*t;
            float* ac = acc[mi][ni];
            float b0 = bias[c], b1 = bias[c+1];
            *(float2*)(Cf + (long long)r0*N + c)     = make_float2(ac[0]+b0, ac[1]+b1);
            *(float2*)(Cf + (long long)(r0+8)*N + c) = make_float2(ac[2]+b0, ac[3]+b1);
        }
    }
}

// ---------------- bf16 m16n8k16 GEMM, reg double-buffered, occ 2 ------------
// A: [M,K] bf16 rm, B: [N,K] bf16 rm. BK=64 bf16 (32 u32 cols, pitch LDT=36).
// EPI 1: Cb = bf16(acc + bias)                      (K, Q)
// EPI 2: Cb = bf16(exp(acc/512)) + fused column-sum partials (E)
template<int EPI>
__global__ void __launch_bounds__(256, 2)
gemm_bf16(const __nv_bfloat16* __restrict__ Ag, const __nv_bfloat16* __restrict__ Bg,
          const float* __restrict__ bias, __nv_bfloat16* __restrict__ Cb,
          float* __restrict__ part,
          int M, int N, int K,
          long long strA, long long strB, long long strC)
{
    __shared__ __align__(16) uint32_t sA[BMT*LDT];
    __shared__ __align__(16) uint32_t sB[BNT*LDT];
    __shared__ float cpart[2][128];

    const int tid  = threadIdx.x;
    const long long bz = blockIdx.z;
    const int bm = blockIdx.y*BMT, bn = blockIdx.x*BNT;
    const int lane = tid & 31, warp = tid >> 5;
    const int wm = (warp & 1)*64, wn = (warp >> 1)*32;
    const int g = lane >> 2, t = lane & 3;
    const int lrow = tid >> 1;                 // 0..127 (staging row)
    const int lch  = (tid & 1)*4;              // 2 threads/row, 4 16B-chunks each

    const __nv_bfloat16* aptr = Ag + bz*strA + (long long)(bm + lrow)*K + lch*8;
    const __nv_bfloat16* bptr = Bg + bz*strB + (long long)(bn + lrow)*K + lch*8;

    float acc[4][4][4];
    #pragma unroll
    for (int i = 0; i < 4; i++)
        #pragma unroll
        for (int j = 0; j < 4; j++)
            #pragma unroll
            for (int c = 0; c < 4; c++) acc[i][j][c] = 0.f;

    // prologue: prefetch tile 0 into registers
    uint4 pa[4], pb[4];
    #pragma unroll
    for (int c = 0; c < 4; c++){
        pa[c] = *(const uint4*)(aptr + c*8);
        pb[c] = *(const uint4*)(bptr + c*8);
    }

    for (int k0 = 0; k0 < K; k0 += 64){
        #pragma unroll
        for (int c = 0; c < 4; c++){
            *(uint4*)&sA[lrow*LDT + (lch + c)*4] = pa[c];
            *(uint4*)&sB[lrow*LDT + (lch + c)*4] = pb[c];
        }
        __syncthreads();
        if (k0 + 64 < K){
            #pragma unroll
            for (int c = 0; c < 4; c++){
                pa[c] = *(const uint4*)(aptr + k0 + 64 + c*8);
                pb[c] = *(const uint4*)(bptr + k0 + 64 + c*8);
            }
        }
        #pragma unroll
        for (int kk = 0; kk < 32; kk += 8){    // each kk = one k16 step
            uint32_t af[4][4], bf[4][2];
            #pragma unroll
            for (int mi = 0; mi < 4; mi++){
                int r = wm + mi*16 + g;
                af[mi][0] = sA[ r    *LDT + kk + t    ];
                af[mi][1] = sA[(r+8) *LDT + kk + t    ];
                af[mi][2] = sA[ r    *LDT + kk + t + 4];
                af[mi][3] = sA[(r+8) *LDT + kk + t + 4];
            }
            #pragma unroll
            for (int ni = 0; ni < 4; ni++){
                int rn = wn + ni*8 + g;
                bf[ni][0] = sB[rn*LDT + kk + t    ];
                bf[ni][1] = sB[rn*LDT + kk + t + 4];
            }
            #pragma unroll
            for (int mi = 0; mi < 4; mi++)
                #pragma unroll
                for (int ni = 0; ni < 4; ni++)
                    mma_bf(acc[mi][ni], af[mi], bf[ni]);
        }
        __syncthreads();
    }

    __nv_bfloat16* Co = Cb + bz*strC;
    if (EPI == 1){
        #pragma unroll
        for (int mi = 0; mi < 4; mi++){
            int r0 = bm + wm + mi*16 + g;
            #pragma unroll
            for (int ni = 0; ni < 4; ni++){
                int c = bn + wn + ni*8 + 2*t;
                float* ac = acc[mi][ni];
                float b0 = bias[c], b1 = bias[c+1];
                *(__nv_bfloat162*)(Co + (long long)r0*N + c) =
                    __floats2bfloat162_rn(ac[0]+b0, ac[1]+b1);
                *(__nv_bfloat162*)(Co + (long long)(r0+8)*N + c) =
                    __floats2bfloat162_rn(ac[2]+b0, ac[3]+b1);
            }
        }
    } else {
        const float inv = 1.0f/512.0f;
        float csum[4][2];
        #pragma unroll
        for (int ni = 0; ni < 4; ni++){ csum[ni][0] = 0.f; csum[ni][1] = 0.f; }

        #pragma unroll
        for (int mi = 0; mi < 4; mi++){
            int r0 = bm + wm + mi*16 + g;
            #pragma unroll
            for (int ni = 0; ni < 4; ni++){
                int c = bn + wn + ni*8 + 2*t;
                float* ac = acc[mi][ni];
                float e0 = __expf(ac[0]*inv), e1 = __expf(ac[1]*inv);
                float e2 = __expf(ac[2]*inv), e3 = __expf(ac[3]*inv);
                *(__nv_bfloat162*)(Co + (long long)r0*N + c)     = __floats2bfloat162_rn(e0, e1);
                *(__nv_bfloat162*)(Co + (long long)(r0+8)*N + c) = __floats2bfloat162_rn(e2, e3);
                csum[ni][0] += e0 + e2;
                csum[ni][1] += e1 + e3;
            }
        }
        // reduce over g (lane bits 2..4): lanes with same t share a column
        #pragma unroll
        for (int m = 4; m <= 16; m <<= 1)
            #pragma unroll
            for (int ni = 0; ni < 4; ni++){
                csum[ni][0] += __shfl_xor_sync(0xffffffffu, csum[ni][0], m);
                csum[ni][1] += __shfl_xor_sync(0xffffffffu, csum[ni][1], m);
            }
        if (lane < 4){   // g == 0; lane == t
            #pragma unroll
            for (int ni = 0; ni < 4; ni++){
                cpart[warp & 1][wn + ni*8 + 2*lane    ] = csum[ni][0];
                cpart[warp & 1][wn + ni*8 + 2*lane + 1] = csum[ni][1];
            }
        }
        __syncthreads();
        if (tid < 128){
            float v = cpart[0][tid] + cpart[1][tid];
            part[((bz*32 + blockIdx.y)*(long long)S_) + bn + tid] = v;
        }
    }
}

// ---------------- Linv from 32 per-tile partials ----------------------------
__global__ void linv_kernel(const float* __restrict__ part, float* __restrict__ Linv){
    int i = blockIdx.x*256 + threadIdx.x;          // b*S + e
    int b = i >> 12, e = i & (S_-1);
    float s = 0.f;
    #pragma unroll
    for (int c = 0; c < 32; c++) s += part[(b*32 + c)*(long long)S_ + e];
    Linv[i] = 1.0f / s;
}

// ---------------- row-sum of E * Linv ---------------------------------------
__global__ void rowsum_kernel(const __nv_bfloat16* __restrict__ E,
                              const float* __restrict__ Linv, float* __restrict__ r){
    int s = blockIdx.x, b = blockIdx.y, tid = threadIdx.x;
    const __nv_bfloat162* row2 = (const __nv_bfloat162*)(E + ((long long)b*S_ + s)*S_);
    const float2* li2 = (const float2*)(Linv + b*S_);
    float acc = 0.f;
    #pragma unroll 4
    for (int i = tid; i < S_/2; i += 256){
        float2 v = __bfloat1622float2(row2[i]);
        float2 l = li2[i];
        acc += v.x*l.x + v.y*l.y;
    }
    __shared__ float red[256];
    red[tid] = acc; __syncthreads();
    for (int st = 128; st > 0; st >>= 1){
        if (tid < st) red[tid] += red[tid + st];
        __syncthreads();
    }
    if (tid == 0) r[(long long)b*S_ + s] = red[0];
}

// ---------------- out = tanh(r * VL + bl) -----------------------------------
__global__ void out_kernel(const float* __restrict__ VL, const float* __restrict__ r,
                           const float* __restrict__ bl, float* __restrict__ out){
    long long i = (long long)blockIdx.x*256 + threadIdx.x;
    float4 v = ((const float4*)VL)[i];
    float rv = r[i >> 7];
    float4 b4 = ((const float4*)bl)[(int)(i & 127)];
    float4 o;
    o.x = tanhf(rv*v.x + b4.x);
    o.y = tanhf(rv*v.y + b4.y);
    o.z = tanhf(rv*v.z + b4.z);
    o.w = tanhf(rv*v.w + b4.w);
    ((float4*)out)[i] = o;
}

// ---------------- launcher --------------------------------------------------
extern "C" void kernel_launch(void* const* d_in, const int* in_sizes, int n_in,
                              void* d_out, int out_size){
    const float* xs = (const float*)d_in[0];
    const float* Wk = (const float*)d_in[1];
    const float* bk = (const float*)d_in[2];
    const float* Wq = (const float*)d_in[3];
    const float* bq = (const float*)d_in[4];
    const float* Wv = (const float*)d_in[5];
    const float* bv = (const float*)d_in[6];
    const float* Wl = (const float*)d_in[7];
    const float* bl = (const float*)d_in[8];
    float* out = (float*)d_out;
    (void)in_sizes; (void)n_in; (void)out_size;

    float *pVL, *pPart, *pLinv, *pR, *pWcP, *pWc, *pBc;
    __nv_bfloat16 *pXh, *pWkh, *pWqh, *pKh, *pQh, *pE;
    cudaGetSymbolAddress((void**)&pXh,   g_Xh);
    cudaGetSymbolAddress((void**)&pWkh,  g_Wkh);
    cudaGetSymbolAddress((void**)&pWqh,  g_Wqh);
    cudaGetSymbolAddress((void**)&pKh,   g_Kh);
    cudaGetSymbolAddress((void**)&pQh,   g_Qh);
    cudaGetSymbolAddress((void**)&pVL,   g_VL);
    cudaGetSymbolAddress((void**)&pE,    g_E);
    cudaGetSymbolAddress((void**)&pPart, g_part);
    cudaGetSymbolAddress((void**)&pLinv, g_Linv);
    cudaGetSymbolAddress((void**)&pR,    g_r);
    cudaGetSymbolAddress((void**)&pWcP,  g_WcP);
    cudaGetSymbolAddress((void**)&pWc,   g_Wc);
    cudaGetSymbolAddress((void**)&pBc,   g_bc);

    // 0) bf16 casts
    cvt_bf16<<<(M1*D_/8)/256, 256>>>((const float4*)xs, (uint4*)pXh);
    cvt_bf16<<<(D_*D_/8)/256, 256>>>((const float4*)Wk, (uint4*)pWkh);
    cvt_bf16<<<(D_*D_/8)/256, 256>>>((const float4*)Wq, (uint4*)pWqh);

    // 1) combined last-layer weights: Wc = Wl@Wv (split-K2), bc = Wl@bv
    wc_gemm<<<dim3(D_/64, D_/64, 2), 256>>>(Wl, Wv, pWcP);
    wc_reduce<<<(D_*D_/4)/256, 256>>>((const float4*)pWcP, (float4*)pWc);
    bc_kernel<<<D_, 128>>>(Wl, bv, pBc);

    // 2) K, Q in bf16 HMMA (reg double-buffered, occ 2)
    gemm_bf16<1><<<dim3(D_/BNT, M1/BMT), 256>>>(pXh, pWkh, bk, pKh, nullptr,
                                                M1, D_, D_, 0, 0, 0);
    gemm_bf16<1><<<dim3(D_/BNT, M1/BMT), 256>>>(pXh, pWqh, bq, pQh, nullptr,
                                                M1, D_, D_, 0, 0, 0);

    // 3) VL in tf32 (accuracy-critical output path, A-prefetched)
    gemm_tf32<<<dim3(D_/BNT, M1/BMT), 256>>>(xs, pWc, pBc, pVL, M1, D_, D_);

    // 4) E[b] = exp((K@Q^T)/512), fused column-sum partials
    gemm_bf16<2><<<dim3(S_/BNT, S_/BMT, B_), 256>>>(pKh, pQh, nullptr, pE, pPart,
                                                    S_, S_, D_,
                                                    (long long)S_*D_, (long long)S_*D_,
                                                    (long long)S_*S_);

    // 5) Linv, r
    linv_kernel<<<(B_*S_)/256, 256>>>(pPart, pLinv);
    rowsum_kernel<<<dim3(S_, B_), 256>>>(pE, pLinv, pR);

    // 6) out = tanh(r * VL + bl)
    out_kernel<<<(B_*S_*D_/4)/256, 256>>>(pVL, pR, bl, out);
}

// round 16
// speedup vs baseline: 1.8176x; 1.0453x over previous
#include <cuda_runtime.h>
#include <cuda_bf16.h>
#include <cstdint>

#define B_ 4
#define S_ 4096
#define D_ 512
#define M1 (B_*S_)   // 16384

// ---------------- scratch (device globals: the sanctioned no-alloc path) ----
__device__ __nv_bfloat16 g_Xh [M1*D_];               // bf16 xs
__device__ __nv_bfloat16 g_Wkh[D_*D_];               // bf16 Wk
__device__ __nv_bfloat16 g_Wqh[D_*D_];               // bf16 Wq
__device__ __nv_bfloat16 g_Kh [B_*S_*D_];            // bf16 K
__device__ __nv_bfloat16 g_Qh [B_*S_*D_];            // bf16 Q
__device__ float         g_VL [B_*S_*D_];
__device__ __nv_bfloat16 g_E  [(size_t)B_*S_*S_];    // E[b][s][e] = exp(qk/512)
__device__ float         g_part[B_*32*S_];           // per-m-tile column sums
__device__ float         g_Linv[B_*S_];
__device__ float         g_r  [B_*S_];
__device__ float         g_WcP[2*D_*D_];             // split-K partials
__device__ float         g_Wc [D_*D_];
__device__ float         g_bc [D_];

// ---------------- helpers ---------------------------------------------------
__device__ __forceinline__ uint32_t f2tf(float x){
    uint32_t r; asm("cvt.rna.tf32.f32 %0, %1;" : "=r"(r) : "f"(x)); return r;
}
__device__ __forceinline__ void mma_tf(float c[4], const uint32_t a[4], const uint32_t b[2]){
    asm volatile(
        "mma.sync.aligned.m16n8k8.row.col.f32.tf32.tf32.f32 "
        "{%0,%1,%2,%3}, {%4,%5,%6,%7}, {%8,%9}, {%0,%1,%2,%3};"
        : "+f"(c[0]), "+f"(c[1]), "+f"(c[2]), "+f"(c[3])
        : "r"(a[0]), "r"(a[1]), "r"(a[2]), "r"(a[3]), "r"(b[0]), "r"(b[1]));
}
__device__ __forceinline__ void mma_bf(float c[4], const uint32_t a[4], const uint32_t b[2]){
    asm volatile(
        "mma.sync.aligned.m16n8k16.row.col.f32.bf16.bf16.f32 "
        "{%0,%1,%2,%3}, {%4,%5,%6,%7}, {%8,%9}, {%0,%1,%2,%3};"
        : "+f"(c[0]), "+f"(c[1]), "+f"(c[2]), "+f"(c[3])
        : "r"(a[0]), "r"(a[1]), "r"(a[2]), "r"(a[3]), "r"(b[0]), "r"(b[1]));
}

// ---------------- float -> bf16 cast (8 elems/thread) ------------------------
__global__ void cvt_bf16(const float4* __restrict__ src, uint4* __restrict__ dst){
    int i = blockIdx.x*256 + threadIdx.x;
    float4 a = src[2*i], b = src[2*i+1];
    __nv_bfloat162 p0 = __floats2bfloat162_rn(a.x, a.y);
    __nv_bfloat162 p1 = __floats2bfloat162_rn(a.z, a.w);
    __nv_bfloat162 p2 = __floats2bfloat162_rn(b.x, b.y);
    __nv_bfloat162 p3 = __floats2bfloat162_rn(b.z, b.w);
    uint4 q;
    q.x = *(uint32_t*)&p0; q.y = *(uint32_t*)&p1;
    q.z = *(uint32_t*)&p2; q.w = *(uint32_t*)&p3;
    dst[i] = q;
}

// ---------------- Wc = Wl @ Wv: split-K x2, reg-prefetched -------------------
__global__ void __launch_bounds__(256)
wc_gemm(const float* __restrict__ Wl, const float* __restrict__ Wv,
        float* __restrict__ WcP){
    __shared__ float sL[16][65];
    __shared__ float sV[16][65];
    const int bj = blockIdx.y*64, bi = blockIdx.x*64;
    const int z  = blockIdx.z;
    const int kbase = z*256;
    const int tx = threadIdx.x & 15, ty = threadIdx.x >> 4;

    float acc[4][4];
    #pragma unroll
    for (int m = 0; m < 4; m++)
        #pragma unroll
        for (int n = 0; n < 4; n++) acc[m][n] = 0.f;

    int rL[4], cL[4], rV[4], cV[4];
    #pragma unroll
    for (int p = 0; p < 4; p++){
        int idx = threadIdx.x + p*256;
        rL[p] = idx >> 4; cL[p] = idx & 15;
        rV[p] = idx >> 6; cV[p] = idx & 63;
    }

    float ra[4], rb[4];
    #pragma unroll
    for (int p = 0; p < 4; p++){
        ra[p] = Wl[(bj + rL[p])*D_ + kbase + cL[p]];
        rb[p] = Wv[(kbase + rV[p])*D_ + bi + cV[p]];
    }

    for (int it = 0; it < 16; it++){
        #pragma unroll
        for (int p = 0; p < 4; p++){
            sL[cL[p]][rL[p]] = ra[p];
            sV[rV[p]][cV[p]] = rb[p];
        }
        __syncthreads();
        if (it < 15){
            int k0 = kbase + (it + 1)*16;
            #pragma unroll
            for (int p = 0; p < 4; p++){
                ra[p] = Wl[(bj + rL[p])*D_ + k0 + cL[p]];
                rb[p] = Wv[(k0 + rV[p])*D_ + bi + cV[p]];
            }
        }
        #pragma unroll
        for (int k = 0; k < 16; k++){
            float a[4], b[4];
            #pragma unroll
            for (int m = 0; m < 4; m++) a[m] = sL[k][ty*4 + m];
            #pragma unroll
            for (int n = 0; n < 4; n++) b[n] = sV[k][tx*4 + n];
            #pragma unroll
            for (int m = 0; m < 4; m++)
                #pragma unroll
                for (int n = 0; n < 4; n++) acc[m][n] += a[m]*b[n];
        }
        __syncthreads();
    }
    #pragma unroll
    for (int m = 0; m < 4; m++)
        #pragma unroll
        for (int n = 0; n < 4; n++)
            WcP[(size_t)z*D_*D_ + (bj + ty*4 + m)*D_ + bi + tx*4 + n] = acc[m][n];
}

__global__ void wc_reduce(const float4* __restrict__ P, float4* __restrict__ Wc){
    int i = blockIdx.x*256 + threadIdx.x;
    float4 a = P[i], b = P[i + D_*D_/4];
    Wc[i] = make_float4(a.x+b.x, a.y+b.y, a.z+b.z, a.w+b.w);
}

// ---------------- bc = Wl @ bv ----------------------------------------------
__global__ void bc_kernel(const float* __restrict__ Wl, const float* __restrict__ bv,
                          float* __restrict__ bc){
    int j = blockIdx.x;
    __shared__ float red[128];
    float a = 0.f;
    for (int k = threadIdx.x; k < D_; k += 128) a += Wl[j*D_ + k]*bv[k];
    red[threadIdx.x] = a; __syncthreads();
    for (int s = 64; s > 0; s >>= 1){
        if (threadIdx.x < s) red[threadIdx.x] += red[threadIdx.x + s];
        __syncthreads();
    }
    if (threadIdx.x == 0) bc[j] = red[0];
}

// ---------------- tf32 mma GEMM (VL path): Cf = A @ B^T + bias --------------
#define BMT 128
#define BNT 128
#define LDT 36   // u32 row pitch with +4 pad: conflict-free LDS/STS

__global__ void __launch_bounds__(256, 2)
gemm_tf32(const float* __restrict__ Ag, const float* __restrict__ Bg,
          const float* __restrict__ bias, float* __restrict__ Cf,
          int M, int N, int K)
{
    __shared__ __align__(16) uint32_t sA[BMT*LDT];
    __shared__ __align__(16) uint32_t sB[BNT*LDT];

    const int tid  = threadIdx.x;
    const int bm = blockIdx.y*BMT, bn = blockIdx.x*BNT;
    const int lane = tid & 31, warp = tid >> 5;
    const int wm = (warp & 1)*64, wn = (warp >> 1)*32;
    const int g = lane >> 2, t = lane & 3;
    const int lrow = tid >> 3, lcol = (tid & 7)*4;

    float acc[4][4][4];
    #pragma unroll
    for (int i = 0; i < 4; i++)
        #pragma unroll
        for (int j = 0; j < 4; j++)
            #pragma unroll
            for (int c = 0; c < 4; c++) acc[i][j][c] = 0.f;

    float4 pa[4];
    #pragma unroll
    for (int p = 0; p < 4; p++)
        pa[p] = *(const float4*)(Ag + (long long)(bm + lrow + p*32)*K + lcol);

    for (int k0 = 0; k0 < K; k0 += 32){
        #pragma unroll
        for (int p = 0; p < 4; p++){
            int r = lrow + p*32;
            *(uint4*)&sA[r*LDT + lcol] =
                make_uint4(f2tf(pa[p].x), f2tf(pa[p].y), f2tf(pa[p].z), f2tf(pa[p].w));
            float4 vb = *(const float4*)(Bg + (long long)(bn + r)*K + k0 + lcol);
            *(uint4*)&sB[r*LDT + lcol] = make_uint4(f2tf(vb.x), f2tf(vb.y), f2tf(vb.z), f2tf(vb.w));
        }
        __syncthreads();
        if (k0 + 32 < K){
            #pragma unroll
            for (int p = 0; p < 4; p++)
                pa[p] = *(const float4*)(Ag + (long long)(bm + lrow + p*32)*K + k0 + 32 + lcol);
        }
        #pragma unroll
        for (int kk = 0; kk < 32; kk += 8){
            uint32_t af[4][4], bf[4][2];
            #pragma unroll
            for (int mi = 0; mi < 4; mi++){
                int r = wm + mi*16 + g;
                af[mi][0] = sA[ r    *LDT + kk + t    ];
                af[mi][1] = sA[(r+8) *LDT + kk + t    ];
                af[mi][2] = sA[ r    *LDT + kk + t + 4];
                af[mi][3] = sA[(r+8) *LDT + kk + t + 4];
            }
            #pragma unroll
            for (int ni = 0; ni < 4; ni++){
                int rn = wn + ni*8 + g;
                bf[ni][0] = sB[rn*LDT + kk + t    ];
                bf[ni][1] = sB[rn*LDT + kk + t + 4];
            }
            #pragma unroll
            for (int mi = 0; mi < 4; mi++)
                #pragma unroll
                for (int ni = 0; ni < 4; ni++)
                    mma_tf(acc[mi][ni], af[mi], bf[ni]);
        }
        __syncthreads();
    }

    #pragma unroll
    for (int mi = 0; mi < 4; mi++){
        int r0 = bm + wm + mi*16 + g;
        #pragma unroll
        for (int ni = 0; ni < 4; ni++){
            int c = bn + wn + ni*8 + 2*t;
            float* ac = acc[mi][ni];
            float b0 = bias[c], b1 = bias[c+1];
            *(float2*)(Cf + (long long)r0*N + c)     = make_float2(ac[0]+b0, ac[1]+b1);
            *(float2*)(Cf + (long long)(r0+8)*N + c) = make_float2(ac[2]+b0, ac[3]+b1);
        }
    }
}

// ---------------- bf16 m16n8k16 GEMM: 2-stage smem double buffer, occ 2 -----
// A: [M,K] bf16 rm, B: [N,K] bf16 rm. BK=64 bf16 (32 u32 cols, pitch LDT=36).
// Mainloop per iter: MMA(stage cur) -> STS(stage next from regs) -> LDG(t+2)
// -> ONE sync. STS rides under MMA issue; LDG has a full MMA block to land.
// EPI 1: z selects (Wk,bk)->Cb or (Wq,bq)->Cb2   (K and Q in one launch)
// EPI 2: Cb = bf16(exp(acc/512)) + fused column-sum partials (E, z = batch)
#define STG_U (2*BMT*LDT)                     // u32 per stage (A+B)
#define GB_SMEM (2*STG_U*4 + 2*128*4)         // 73728 + 1024 bytes

template<int EPI>
__global__ void __launch_bounds__(256, 2)
gemm_bf16(const __nv_bfloat16* __restrict__ Ag, const __nv_bfloat16* __restrict__ Bg,
          const __nv_bfloat16* __restrict__ Bg2,
          const float* __restrict__ bias, const float* __restrict__ bias2,
          __nv_bfloat16* __restrict__ Cb, __nv_bfloat16* __restrict__ Cb2,
          float* __restrict__ part,
          int M, int N, int K,
          long long strA, long long strB, long long strC)
{
    extern __shared__ __align__(16) uint32_t smx[];
    float* cpart = (float*)(smx + 2*STG_U);   // [2][128]

    const int tid  = threadIdx.x;
    const int z = blockIdx.z;
    const int bm = blockIdx.y*BMT, bn = blockIdx.x*BNT;
    const int lane = tid & 31, warp = tid >> 5;
    const int wm = (warp & 1)*64, wn = (warp >> 1)*32;
    const int g = lane >> 2, t = lane & 3;
    const int lrow = tid >> 1;                 // 0..127 (staging row)
    const int lch  = (tid & 1)*4;              // 2 threads/row, 4 16B-chunks each

    const __nv_bfloat16* Asel;
    const __nv_bfloat16* Bsel;
    if (EPI == 1){ Asel = Ag; Bsel = z ? Bg2 : Bg; }
    else         { Asel = Ag + (long long)z*strA; Bsel = Bg + (long long)z*strB; }

    const __nv_bfloat16* aptr = Asel + (long long)(bm + lrow)*K + lch*8;
    const __nv_bfloat16* bptr = Bsel + (long long)(bn + lrow)*K + lch*8;
    const int sidx = lrow*LDT + lch*4;
    const int NT = K >> 6;                     // k-tiles of 64

    float acc[4][4][4];
    #pragma unroll
    for (int i = 0; i < 4; i++)
        #pragma unroll
        for (int j = 0; j < 4; j++)
            #pragma unroll
            for (int c = 0; c < 4; c++) acc[i][j][c] = 0.f;

    uint4 pa[4], pb[4];
    // tile 0 -> regs -> stage 0
    #pragma unroll
    for (int c = 0; c < 4; c++){
        pa[c] = *(const uint4*)(aptr + c*8);
        pb[c] = *(const uint4*)(bptr + c*8);
    }
    #pragma unroll
    for (int c = 0; c < 4; c++){
        *(uint4*)&smx[sidx + c*4]             = pa[c];
        *(uint4*)&smx[BMT*LDT + sidx + c*4]   = pb[c];
    }
    // tile 1 -> regs
    if (NT > 1){
        #pragma unroll
        for (int c = 0; c < 4; c++){
            pa[c] = *(const uint4*)(aptr + 64 + c*8);
            pb[c] = *(const uint4*)(bptr + 64 + c*8);
        }
    }
    __syncthreads();

    for (int it = 0; it < NT; it++){
        const uint32_t* sA = smx + (it & 1)*STG_U;
        const uint32_t* sB = sA + BMT*LDT;
        #pragma unroll
        for (int kk = 0; kk < 32; kk += 8){    // each kk = one k16 step
            uint32_t af[4][4], bf[4][2];
            #pragma unroll
            for (int mi = 0; mi < 4; mi++){
                int r = wm + mi*16 + g;
                af[mi][0] = sA[ r    *LDT + kk + t    ];
                af[mi][1] = sA[(r+8) *LDT + kk + t    ];
                af[mi][2] = sA[ r    *LDT + kk + t + 4];
                af[mi][3] = sA[(r+8) *LDT + kk + t + 4];
            }
            #pragma unroll
            for (int ni = 0; ni < 4; ni++){
                int rn = wn + ni*8 + g;
                bf[ni][0] = sB[rn*LDT + kk + t    ];
                bf[ni][1] = sB[rn*LDT + kk + t + 4];
            }
            #pragma unroll
            for (int mi = 0; mi < 4; mi++)
                #pragma unroll
                for (int ni = 0; ni < 4; ni++)
                    mma_bf(acc[mi][ni], af[mi], bf[ni]);
        }
        if (it + 1 < NT){
            uint32_t* dA = smx + ((it + 1) & 1)*STG_U;
            #pragma unroll
            for (int c = 0; c < 4; c++){
                *(uint4*)&dA[sidx + c*4]           = pa[c];
                *(uint4*)&dA[BMT*LDT + sidx + c*4] = pb[c];
            }
            if (it + 2 < NT){
                #pragma unroll
                for (int c = 0; c < 4; c++){
                    pa[c] = *(const uint4*)(aptr + (it + 2)*64 + c*8);
                    pb[c] = *(const uint4*)(bptr + (it + 2)*64 + c*8);
                }
            }
        }
        __syncthreads();
    }

    if (EPI == 1){
        const float*   bsel = z ? bias2 : bias;
        __nv_bfloat16* Co   = z ? Cb2   : Cb;
        #pragma unroll
        for (int mi = 0; mi < 4; mi++){
            int r0 = bm + wm + mi*16 + g;
            #pragma unroll
            for (int ni = 0; ni < 4; ni++){
                int c = bn + wn + ni*8 + 2*t;
                float* ac = acc[mi][ni];
                float b0 = bsel[c], b1 = bsel[c+1];
                *(__nv_bfloat162*)(Co + (long long)r0*N + c) =
                    __floats2bfloat162_rn(ac[0]+b0, ac[1]+b1);
                *(__nv_bfloat162*)(Co + (long long)(r0+8)*N + c) =
                    __floats2bfloat162_rn(ac[2]+b0, ac[3]+b1);
            }
        }
    } else {
        __nv_bfloat16* Co = Cb + (long long)z*strC;
        const float inv = 1.0f/512.0f;
        float csum[4][2];
        #pragma unroll
        for (int ni = 0; ni < 4; ni++){ csum[ni][0] = 0.f; csum[ni][1] = 0.f; }

        #pragma unroll
        for (int mi = 0; mi < 4; mi++){
            int r0 = bm + wm + mi*16 + g;
            #pragma unroll
            for (int ni = 0; ni < 4; ni++){
                int c = bn + wn + ni*8 + 2*t;
                float* ac = acc[mi][ni];
                float e0 = __expf(ac[0]*inv), e1 = __expf(ac[1]*inv);
                float e2 = __expf(ac[2]*inv), e3 = __expf(ac[3]*inv);
                *(__nv_bfloat162*)(Co + (long long)r0*N + c)     = __floats2bfloat162_rn(e0, e1);
                *(__nv_bfloat162*)(Co + (long long)(r0+8)*N + c) = __floats2bfloat162_rn(e2, e3);
                csum[ni][0] += e0 + e2;
                csum[ni][1] += e1 + e3;
            }
        }
        #pragma unroll
        for (int m = 4; m <= 16; m <<= 1)
            #pragma unroll
            for (int ni = 0; ni < 4; ni++){
                csum[ni][0] += __shfl_xor_sync(0xffffffffu, csum[ni][0], m);
                csum[ni][1] += __shfl_xor_sync(0xffffffffu, csum[ni][1], m);
            }
        if (lane < 4){   // g == 0; lane == t
            #pragma unroll
            for (int ni = 0; ni < 4; ni++){
                cpart[(warp & 1)*128 + wn + ni*8 + 2*lane    ] = csum[ni][0];
                cpart[(warp & 1)*128 + wn + ni*8 + 2*lane + 1] = csum[ni][1];
            }
        }
        __syncthreads();
        if (tid < 128){
            float v = cpart[tid] + cpart[128 + tid];
            part[(((long long)z*32 + blockIdx.y)*(long long)S_) + bn + tid] = v;
        }
    }
}

// ---------------- Linv from 32 per-tile partials ----------------------------
__global__ void linv_kernel(const float* __restrict__ part, float* __restrict__ Linv){
    int i = blockIdx.x*256 + threadIdx.x;          // b*S + e
    int b = i >> 12, e = i & (S_-1);
    float s = 0.f;
    #pragma unroll
    for (int c = 0; c < 32; c++) s += part[(b*32 + c)*(long long)S_ + e];
    Linv[i] = 1.0f / s;
}

// ---------------- row-sum of E * Linv ---------------------------------------
__global__ void rowsum_kernel(const __nv_bfloat16* __restrict__ E,
                              const float* __restrict__ Linv, float* __restrict__ r){
    int s = blockIdx.x, b = blockIdx.y, tid = threadIdx.x;
    const __nv_bfloat162* row2 = (const __nv_bfloat162*)(E + ((long long)b*S_ + s)*S_);
    const float2* li2 = (const float2*)(Linv + b*S_);
    float acc = 0.f;
    #pragma unroll 4
    for (int i = tid; i < S_/2; i += 256){
        float2 v = __bfloat1622float2(row2[i]);
        float2 l = li2[i];
        acc += v.x*l.x + v.y*l.y;
    }
    __shared__ float red[256];
    red[tid] = acc; __syncthreads();
    for (int st = 128; st > 0; st >>= 1){
        if (tid < st) red[tid] += red[tid + st];
        __syncthreads();
    }
    if (tid == 0) r[(long long)b*S_ + s] = red[0];
}

// ---------------- out = tanh(r * VL + bl) -----------------------------------
__global__ void out_kernel(const float* __restrict__ VL, const float* __restrict__ r,
                           const float* __restrict__ bl, float* __restrict__ out){
    long long i = (long long)blockIdx.x*256 + threadIdx.x;
    float4 v = ((const float4*)VL)[i];
    float rv = r[i >> 7];
    float4 b4 = ((const float4*)bl)[(int)(i & 127)];
    float4 o;
    o.x = tanhf(rv*v.x + b4.x);
    o.y = tanhf(rv*v.y + b4.y);
    o.z = tanhf(rv*v.z + b4.z);
    o.w = tanhf(rv*v.w + b4.w);
    ((float4*)out)[i] = o;
}

// ---------------- launcher --------------------------------------------------
extern "C" void kernel_launch(void* const* d_in, const int* in_sizes, int n_in,
                              void* d_out, int out_size){
    const float* xs = (const float*)d_in[0];
    const float* Wk = (const float*)d_in[1];
    const float* bk = (const float*)d_in[2];
    const float* Wq = (const float*)d_in[3];
    const float* bq = (const float*)d_in[4];
    const float* Wv = (const float*)d_in[5];
    const float* bv = (const float*)d_in[6];
    const float* Wl = (const float*)d_in[7];
    const float* bl = (const float*)d_in[8];
    float* out = (float*)d_out;
    (void)in_sizes; (void)n_in; (void)out_size;

    float *pVL, *pPart, *pLinv, *pR, *pWcP, *pWc, *pBc;
    __nv_bfloat16 *pXh, *pWkh, *pWqh, *pKh, *pQh, *pE;
    cudaGetSymbolAddress((void**)&pXh,   g_Xh);
    cudaGetSymbolAddress((void**)&pWkh,  g_Wkh);
    cudaGetSymbolAddress((void**)&pWqh,  g_Wqh);
    cudaGetSymbolAddress((void**)&pKh,   g_Kh);
    cudaGetSymbolAddress((void**)&pQh,   g_Qh);
    cudaGetSymbolAddress((void**)&pVL,   g_VL);
    cudaGetSymbolAddress((void**)&pE,    g_E);
    cudaGetSymbolAddress((void**)&pPart, g_part);
    cudaGetSymbolAddress((void**)&pLinv, g_Linv);
    cudaGetSymbolAddress((void**)&pR,    g_r);
    cudaGetSymbolAddress((void**)&pWcP,  g_WcP);
    cudaGetSymbolAddress((void**)&pWc,   g_Wc);
    cudaGetSymbolAddress((void**)&pBc,   g_bc);

    static bool attr_done = false;
    if (!attr_done){
        cudaFuncSetAttribute(gemm_bf16<1>, cudaFuncAttributeMaxDynamicSharedMemorySize, GB_SMEM);
        cudaFuncSetAttribute(gemm_bf16<2>, cudaFuncAttributeMaxDynamicSharedMemorySize, GB_SMEM);
        attr_done = true;
    }

    // 0) bf16 casts
    cvt_bf16<<<(M1*D_/8)/256, 256>>>((const float4*)xs, (uint4*)pXh);
    cvt_bf16<<<(D_*D_/8)/256, 256>>>((const float4*)Wk, (uint4*)pWkh);
    cvt_bf16<<<(D_*D_/8)/256, 256>>>((const float4*)Wq, (uint4*)pWqh);

    // 1) combined last-layer weights: Wc = Wl@Wv (split-K2), bc = Wl@bv
    wc_gemm<<<dim3(D_/64, D_/64, 2), 256>>>(Wl, Wv, pWcP);
    wc_reduce<<<(D_*D_/4)/256, 256>>>((const float4*)pWcP, (float4*)pWc);
    bc_kernel<<<D_, 128>>>(Wl, bv, pBc);

    // 2) K and Q fused in one bf16 HMMA launch (z selects weight/bias/output)
    gemm_bf16<1><<<dim3(D_/BNT, M1/BMT, 2), 256, GB_SMEM>>>(
        pXh, pWkh, pWqh, bk, bq, pKh, pQh, nullptr, M1, D_, D_, 0, 0, 0);

    // 3) VL in tf32 (accuracy-critical output path, A-prefetched)
    gemm_tf32<<<dim3(D_/BNT, M1/BMT), 256>>>(xs, pWc, pBc, pVL, M1, D_, D_);

    // 4) E[b] = exp((K@Q^T)/512), fused column-sum partials
    gemm_bf16<2><<<dim3(S_/BNT, S_/BMT, B_), 256, GB_SMEM>>>(
        pKh, pQh, nullptr, nullptr, nullptr, pE, nullptr, pPart,
        S_, S_, D_, (long long)S_*D_, (long long)S_*D_, (long long)S_*S_);

    // 5) Linv, r
    linv_kernel<<<(B_*S_)/256, 256>>>(pPart, pLinv);
    rowsum_kernel<<<dim3(S_, B_), 256>>>(pE, pLinv, pR);

    // 6) out = tanh(r * VL + bl)
    out_kernel<<<(B_*S_*D_/4)/256, 256>>>(pVL, pR, bl, out);
}